// round 11
// baseline (speedup 1.0000x reference)
#include <cuda_runtime.h>
#include <cuda_fp16.h>
#include <math.h>
#include <stdint.h>

#define D_  1024
#define H_  16
#define DH_ 64
#define P_  16
#define C_  512
#define B_  4
#define S_  4096
#define FF_ 4096
#define NC_ 8
#define BC_ (B_*C_)      /* 2048 */
#define PCP_ 640         /* padded key length (5*128) */
#define BH_ (B_*H_)      /* 64   */

static constexpr long KB_OFF = (long)BH_ * C_ * DH_;
static constexpr long VB_OFF = KB_OFF + (long)BH_ * PCP_ * DH_;
static constexpr long ATTN_SZ = VB_OFF + (long)BH_ * DH_ * PCP_;

// ------------------------- scratch (device globals) -------------------------
__device__ __align__(16) __half g_h1[BC_*D_];
__device__ __align__(16) __half g_qkvm[(long)BC_*3*D_];   // qm|km|vm (half)
__device__ float g_mc[BC_*D_];
__device__ float g_pr[BC_*D_];
__device__ float g_grad[B_*D_*D_];
__device__ float g_Mst[B_*D_*D_];
__device__ float g_Sst[B_*D_*D_];
__device__ __align__(16) __half g_h2[BC_*D_];
__device__ __align__(16) __half g_attn[(size_t)ATTN_SZ]; // qb | kb | vbT
__device__ float g_sc[(long)BH_*C_*PCP_];
__device__ __align__(16) __half g_scp[(long)BH_*C_*PCP_];
__device__ __align__(16) __half g_atg[(long)2*BC_*D_];   // at | mch
__device__ float g_aogt[(long)2*BC_*D_];                 // ao | gt
__device__ float g_o [BC_*D_];
__device__ __align__(16) __half g_h3[BC_*D_];
__device__ __align__(16) __half g_fs[(long)BC_*FF_];

// half operand buffers ([N,K] K-major for mma B operand)
__device__ __align__(16) __half w_mem[(long)3*D_*D_];
__device__ __align__(16) __half w_qkv[(long)3*D_*D_];
__device__ __align__(16) __half w_og[(long)2*D_*D_];     // Wo^T | Wg^T
__device__ __align__(16) __half w_gui[(long)2*FF_*D_];   // interleaved gate/up
__device__ __align__(16) __half w_down[(long)D_*FF_];
__device__ __align__(16) __half t_M [B_*D_*D_];
__device__ __align__(16) __half t_km[(long)B_*D_*C_];
__device__ __align__(16) __half t_pr[(long)B_*D_*C_];
__device__ float b_qkv[3*D_];
__device__ float b_gui[2*FF_];
__device__ float b_og[2*D_];

// ----------------------------- PTX helpers ----------------------------------
__device__ __forceinline__ uint32_t smem_u32(const void* p) {
    uint32_t a;
    asm("{ .reg .u64 t; cvta.to.shared.u64 t, %1; cvt.u32.u64 %0, t; }"
        : "=r"(a) : "l"(p));
    return a;
}
__device__ __forceinline__ void ldsm4(uint32_t& r0, uint32_t& r1, uint32_t& r2,
                                      uint32_t& r3, uint32_t addr) {
    asm volatile("ldmatrix.sync.aligned.m8n8.x4.shared.b16 {%0,%1,%2,%3}, [%4];"
                 : "=r"(r0), "=r"(r1), "=r"(r2), "=r"(r3) : "r"(addr));
}
#define CP_ASYNC16(dst, src)                                                     \
    asm volatile("cp.async.cg.shared.global [%0], [%1], 16;" :: "r"(dst), "l"(src))
#define CP_COMMIT()  asm volatile("cp.async.commit_group;")
#define CP_WAIT(n)   asm volatile("cp.async.wait_group %0;" :: "n"(n))

#define MMAH(d, a, b0, b1)                                                       \
    asm volatile(                                                                \
        "mma.sync.aligned.m16n8k16.row.col.f32.f16.f16.f32 "                     \
        "{%0,%1,%2,%3}, {%4,%5,%6,%7}, {%8,%9}, {%0,%1,%2,%3};"                  \
        : "+f"((d)[0]), "+f"((d)[1]), "+f"((d)[2]), "+f"((d)[3])                 \
        : "r"((a)[0]), "r"((a)[1]), "r"((a)[2]), "r"((a)[3]), "r"(b0), "r"(b1))

// -------------------- FP16 HMMA GEMM, cp.async 4-stage ----------------------
// C = epi(alpha * A[M,K] @ B[N,K]^T). A,B pre-rounded __half. fp32 accum.
// EPI: 0 plain fp32; 1 +bias fp32; 5 C+=acc+bias & outp; 9 half store;
//      10 +bias half qkv-scatter; 12 interleaved silu(gate)*up -> half;
//      14 dual Wo/Wg (z=0 +bias, z=1 sigmoid+bias); 15 merged mc|pr (z=0..7).
#define LDH_ 40
#define HT_ (128 * LDH_)
#define NSTG_ 4
#define TM_SMEM (NSTG_ * 2 * HT_ * 2)   /* 81920 B */

template<int EPI>
__global__ __launch_bounds__(256, 2) void hmma_k(
    const __half* __restrict__ A, const __half* __restrict__ Bw,
    float* __restrict__ Cm, const float* __restrict__ bias,
    void* __restrict__ aux, int ldc, int K, int lda,
    long sA, long sB, long sC, float alpha, int c0)
{
    extern __shared__ __half smh[];
    const int bz = blockIdx.z;
    if (EPI == 15) {
        A  = g_qkvm + (long)(bz & 3) * ((long)C_ * 3 * D_) + ((bz >> 2) ? D_ : 0);
        Bw = t_M + (long)(bz & 3) * ((long)D_ * D_);
    } else {
        A  += bz * sA;
        Bw += bz * sB;
        Cm += bz * sC;
        if (EPI == 14) bias += (long)bz * ldc;
    }

    const int tid = threadIdx.x, warp = tid >> 5, lane = tid & 31;
    const int n0 = blockIdx.x * 128, m0 = blockIdx.y * 128;
    const int mo = (warp >> 2) * 64, no = (warp & 3) * 32;
    const int grp = lane >> 2, tig = lane & 3;
    const int lrow = lane & 15, lcol = (lane >> 4) << 3;

    const int lr = tid >> 1;
    const int lc = (tid & 1) << 4;   // halves

    float acc[4][4][4] = {};
    const int KT = K >> 5;

#pragma unroll
    for (int s = 0; s < NSTG_ - 1; s++) {
        const int k0 = s << 5;
        __half* As = smh + s * 2 * HT_;
        __half* Bs = As + HT_;
#pragma unroll
        for (int j = 0; j < 2; j++) {
            CP_ASYNC16(smem_u32(&As[lr * LDH_ + lc + 8 * j]), A  + (long)(m0 + lr) * lda + k0 + lc + 8 * j);
            CP_ASYNC16(smem_u32(&Bs[lr * LDH_ + lc + 8 * j]), Bw + (long)(n0 + lr) * K + k0 + lc + 8 * j);
        }
        CP_COMMIT();
    }

    for (int kt = 0; kt < KT; kt++) {
        if (kt + 1 < KT) { CP_WAIT(NSTG_ - 2); } else { CP_WAIT(0); }
        __syncthreads();

        if (kt + NSTG_ - 1 < KT) {
            const int s = (kt + NSTG_ - 1) % NSTG_;
            const int k0 = (kt + NSTG_ - 1) << 5;
            __half* As = smh + s * 2 * HT_;
            __half* Bs = As + HT_;
#pragma unroll
            for (int j = 0; j < 2; j++) {
                CP_ASYNC16(smem_u32(&As[lr * LDH_ + lc + 8 * j]), A  + (long)(m0 + lr) * lda + k0 + lc + 8 * j);
                CP_ASYNC16(smem_u32(&Bs[lr * LDH_ + lc + 8 * j]), Bw + (long)(n0 + lr) * K + k0 + lc + 8 * j);
            }
            CP_COMMIT();
        }

        const __half* As = smh + (kt % NSTG_) * 2 * HT_;
        const __half* Bs = As + HT_;
        const uint32_t uA = smem_u32(As);
#pragma unroll
        for (int h = 0; h < 2; h++) {
            uint32_t a[4][4], q[8];
#pragma unroll
            for (int mt = 0; mt < 4; mt++) {
                uint32_t ad = uA + (uint32_t)(((mo + mt * 16 + lrow) * LDH_ + h * 16 + lcol) * 2);
                ldsm4(a[mt][0], a[mt][1], a[mt][2], a[mt][3], ad);
            }
#pragma unroll
            for (int g = 0; g < 2; g++) {
                uint32_t bd = smem_u32(&Bs[(no + g * 16 + lrow) * LDH_ + h * 16 + lcol]);
                ldsm4(q[g * 4 + 0], q[g * 4 + 1], q[g * 4 + 2], q[g * 4 + 3], bd);
            }
#pragma unroll
            for (int mt = 0; mt < 4; mt++)
#pragma unroll
                for (int j = 0; j < 4; j++) {
                    uint32_t b0 = q[(j >> 1) * 4 + (j & 1)];
                    uint32_t b1 = q[(j >> 1) * 4 + (j & 1) + 2];
                    MMAH(acc[mt][j], a[mt], b0, b1);
                }
        }
    }

    // ------------------------------ epilogue --------------------------------
#pragma unroll
    for (int mt = 0; mt < 4; mt++) {
#pragma unroll
        for (int j = 0; j < 4; j++) {
            int row = m0 + mo + mt * 16 + grp;
            int col = n0 + no + j * 8 + tig * 2;
#pragma unroll
            for (int hh = 0; hh < 2; hh++) {
                int r = row + hh * 8;
                float v0 = acc[mt][j][hh * 2 + 0] * alpha;
                float v1 = acc[mt][j][hh * 2 + 1] * alpha;
                if (EPI == 1 || EPI == 5 || EPI == 10 || EPI == 12 || EPI == 14) {
                    float2 bv = *(const float2*)(bias + col);
                    v0 += bv.x; v1 += bv.y;
                }
                if (EPI == 9) {
                    __half* Ch = (__half*)Cm;
                    *(__half2*)(Ch + (long)r * ldc + col) = __floats2half2_rn(v0, v1);
                } else if (EPI == 10) {
                    __half* Ch = (__half*)Cm;
                    int b = r >> 9, i = r & 511;
                    int seg = col >> 10, cl = col & 1023;
                    int h = cl >> 6, d = cl & 63;
                    __half2 o = __floats2half2_rn(v0, v1);
                    if (seg == 0)
                        *(__half2*)(Ch + ((((long)b * H_ + h) * C_ + i) * DH_ + d)) = o;
                    else if (seg == 1)
                        *(__half2*)(Ch + KB_OFF + ((((long)b * H_ + h) * PCP_ + P_ + i) * DH_ + d)) = o;
                    else {
                        Ch[VB_OFF + (((long)b * H_ + h) * DH_ + d)     * PCP_ + P_ + i] = __float2half_rn(v0);
                        Ch[VB_OFF + (((long)b * H_ + h) * DH_ + d + 1) * PCP_ + P_ + i] = __float2half_rn(v1);
                    }
                } else if (EPI == 12) {
                    // v0 = gate, v1 = up (interleaved weights)
                    float sg = v0 / (1.f + expf(-v0));
                    ((__half*)Cm)[(long)r * ldc + (col >> 1)] = __float2half_rn(sg * v1);
                } else if (EPI == 15) {
                    int bb = bz & 3, path = bz >> 2;
                    long rg = (long)bb * C_ + r;
                    if (path == 0) {
                        float2 o; o.x = v0; o.y = v1;
                        *(float2*)(g_mc + rg * D_ + col) = o;
                        *(__half2*)(g_atg + (long)BC_ * D_ + rg * D_ + col) = __floats2half2_rn(v0, v1);
                    } else {
                        float2 vm = __half22float2(*(const __half2*)(g_qkvm + rg * 3 * D_ + 2 * D_ + col));
                        v0 -= vm.x; v1 -= vm.y;
                        float2 o; o.x = v0; o.y = v1;
                        *(float2*)(g_pr + rg * D_ + col) = o;
                    }
                } else if (EPI == 14) {
                    if (bz != 0) {
                        v0 = 1.f / (1.f + expf(-v0));
                        v1 = 1.f / (1.f + expf(-v1));
                    }
                    float2 o; o.x = v0; o.y = v1;
                    *(float2*)(Cm + (long)r * ldc + col) = o;
                } else {
                    float* cp = Cm + (long)r * ldc + col;
                    if (EPI == 5) {
                        float2 c = *(float2*)cp;
                        v0 += c.x; v1 += c.y;
                    }
                    float2 o; o.x = v0; o.y = v1;
                    *(float2*)cp = o;
                    if (EPI == 5) {
                        int b = r >> 9, i = r & 511;
                        *(float2*)((float*)aux + ((long)b * S_ + c0 + i) * D_ + col) = o;
                    }
                }
            }
        }
    }
}

// ------------------ attention scores: S = Q @ K^T * 0.125 + mask ------------
#define SC_LD 72
#define SC_SMEM (2 * 128 * SC_LD * 2)   /* 36864 B */
__global__ __launch_bounds__(256, 2) void attn_sc_k(
    const __half* __restrict__ qb, const __half* __restrict__ kb,
    float* __restrict__ sc)
{
    extern __shared__ __half smh[];
    __half* As = smh;
    __half* Bs = smh + 128 * SC_LD;
    const int bh = blockIdx.z;
    const int n0 = blockIdx.x * 128, m0 = blockIdx.y * 128;
    const __half* Aq = qb + (long)bh * C_ * DH_;
    const __half* Bk = kb + (long)bh * PCP_ * DH_;

    const int tid = threadIdx.x, warp = tid >> 5, lane = tid & 31;
    const int mo = (warp >> 2) * 64, no = (warp & 3) * 32;
    const int grp = lane >> 2, tig = lane & 3;
    const int lrow = lane & 15, lcol = (lane >> 4) << 3;
    const int lr = tid >> 1, lc = (tid & 1) << 5;

    float acc[4][4][4] = {};

#pragma unroll
    for (int j = 0; j < 4; j++) {
        CP_ASYNC16(smem_u32(&As[lr * SC_LD + lc + 8 * j]), Aq + (long)(m0 + lr) * DH_ + lc + 8 * j);
        CP_ASYNC16(smem_u32(&Bs[lr * SC_LD + lc + 8 * j]), Bk + (long)(n0 + lr) * DH_ + lc + 8 * j);
    }
    CP_COMMIT();
    CP_WAIT(0);
    __syncthreads();

    const uint32_t uA = smem_u32(As);
#pragma unroll
    for (int h = 0; h < 4; h++) {
        uint32_t a[4][4], q[8];
#pragma unroll
        for (int mt = 0; mt < 4; mt++) {
            uint32_t ad = uA + (uint32_t)(((mo + mt * 16 + lrow) * SC_LD + h * 16 + lcol) * 2);
            ldsm4(a[mt][0], a[mt][1], a[mt][2], a[mt][3], ad);
        }
#pragma unroll
        for (int g = 0; g < 2; g++) {
            uint32_t bd = smem_u32(&Bs[(no + g * 16 + lrow) * SC_LD + h * 16 + lcol]);
            ldsm4(q[g * 4 + 0], q[g * 4 + 1], q[g * 4 + 2], q[g * 4 + 3], bd);
        }
#pragma unroll
        for (int mt = 0; mt < 4; mt++)
#pragma unroll
            for (int j = 0; j < 4; j++) {
                uint32_t b0 = q[(j >> 1) * 4 + (j & 1)];
                uint32_t b1 = q[(j >> 1) * 4 + (j & 1) + 2];
                MMAH(acc[mt][j], a[mt], b0, b1);
            }
    }

#pragma unroll
    for (int mt = 0; mt < 4; mt++) {
#pragma unroll
        for (int j = 0; j < 4; j++) {
            int row = m0 + mo + mt * 16 + grp;
            int col = n0 + no + j * 8 + tig * 2;
#pragma unroll
            for (int hh = 0; hh < 2; hh++) {
                int gi = row + hh * 8;
                float2 o;
                o.x = (col     < P_ || (col     - P_) <= gi) ? acc[mt][j][hh*2+0] * 0.125f : -1e9f;
                o.y = (col + 1 < P_ || (col + 1 - P_) <= gi) ? acc[mt][j][hh*2+1] * 0.125f : -1e9f;
                *(float2*)(sc + ((long)bh * C_ + gi) * PCP_ + col) = o;
            }
        }
    }
}

// ------------------- attention AV: O = P @ V (half) -------------------------
#define AV_AT (128 * LDH_)
#define AV_BT (64 * LDH_)
#define AV_ST (AV_AT + AV_BT)
#define AV_SMEM (3 * AV_ST * 2)
__global__ __launch_bounds__(256, 2) void attn_av_k(
    const __half* __restrict__ scp, const __half* __restrict__ vbT,
    __half* __restrict__ at)
{
    extern __shared__ __half smh[];
    const int bh = blockIdx.y, b = bh >> 4, h = bh & 15;
    const int m0 = blockIdx.x * 128;
    const __half* Ap = scp + ((long)bh * C_ + m0) * PCP_;
    const __half* Bv = vbT + (long)bh * DH_ * PCP_;

    const int tid = threadIdx.x, warp = tid >> 5, lane = tid & 31;
    const int mo = (warp & 3) * 32, no = (warp >> 2) * 32;
    const int grp = lane >> 2, tig = lane & 3;
    const int lrow = lane & 15, lcol = (lane >> 4) << 3;
    const int lra = tid >> 1, lca = (tid & 1) << 4;
    const int lrb = tid >> 2, lcb = (tid & 3) << 3;

    float acc[2][4][4] = {};
    const int KT = PCP_ >> 5;

#pragma unroll
    for (int s = 0; s < 2; s++) {
        const int k0 = s << 5;
        __half* As = smh + s * AV_ST;
        __half* Bs = As + AV_AT;
#pragma unroll
        for (int j = 0; j < 2; j++)
            CP_ASYNC16(smem_u32(&As[lra * LDH_ + lca + 8 * j]), Ap + (long)lra * PCP_ + k0 + lca + 8 * j);
        CP_ASYNC16(smem_u32(&Bs[lrb * LDH_ + lcb]), Bv + (long)lrb * PCP_ + k0 + lcb);
        CP_COMMIT();
    }

    for (int kt = 0; kt < KT; kt++) {
        if (kt + 1 < KT) { CP_WAIT(1); } else { CP_WAIT(0); }
        __syncthreads();
        if (kt + 2 < KT) {
            const int s = (kt + 2) % 3;
            const int k0 = (kt + 2) << 5;
            __half* As = smh + s * AV_ST;
            __half* Bs = As + AV_AT;
#pragma unroll
            for (int j = 0; j < 2; j++)
                CP_ASYNC16(smem_u32(&As[lra * LDH_ + lca + 8 * j]), Ap + (long)lra * PCP_ + k0 + lca + 8 * j);
            CP_ASYNC16(smem_u32(&Bs[lrb * LDH_ + lcb]), Bv + (long)lrb * PCP_ + k0 + lcb);
            CP_COMMIT();
        }

        const __half* As = smh + (kt % 3) * AV_ST;
        const __half* Bs = As + AV_AT;
        const uint32_t uA = smem_u32(As);
#pragma unroll
        for (int h2 = 0; h2 < 2; h2++) {
            uint32_t a[2][4], q[8];
#pragma unroll
            for (int mt = 0; mt < 2; mt++) {
                uint32_t ad = uA + (uint32_t)(((mo + mt * 16 + lrow) * LDH_ + h2 * 16 + lcol) * 2);
                ldsm4(a[mt][0], a[mt][1], a[mt][2], a[mt][3], ad);
            }
#pragma unroll
            for (int g = 0; g < 2; g++) {
                uint32_t bd = smem_u32(&Bs[(no + g * 16 + lrow) * LDH_ + h2 * 16 + lcol]);
                ldsm4(q[g * 4 + 0], q[g * 4 + 1], q[g * 4 + 2], q[g * 4 + 3], bd);
            }
#pragma unroll
            for (int mt = 0; mt < 2; mt++)
#pragma unroll
                for (int j = 0; j < 4; j++) {
                    uint32_t b0 = q[(j >> 1) * 4 + (j & 1)];
                    uint32_t b1 = q[(j >> 1) * 4 + (j & 1) + 2];
                    MMAH(acc[mt][j], a[mt], b0, b1);
                }
        }
    }

#pragma unroll
    for (int mt = 0; mt < 2; mt++) {
#pragma unroll
        for (int j = 0; j < 4; j++) {
            int row = m0 + mo + mt * 16 + grp;
            int col = no + j * 8 + tig * 2;
#pragma unroll
            for (int hh = 0; hh < 2; hh++) {
                int gi = row + hh * 8;
                *(__half2*)(at + ((long)b * C_ + gi) * D_ + h * DH_ + col) =
                    __floats2half2_rn(acc[mt][j][hh * 2 + 0], acc[mt][j][hh * 2 + 1]);
            }
        }
    }
}

// ------------------- transpose converts -------------------------------------
__global__ __launch_bounds__(256) void tconvfh_k(
    const float* __restrict__ in, __half* __restrict__ out,
    int R, int ldin, long sIn, long sOut)
{
    __shared__ float t[32][33];
    in  += (long)blockIdx.z * sIn;
    out += (long)blockIdx.z * sOut;
    int r0 = blockIdx.y * 32, c0 = blockIdx.x * 32;
    int tx = threadIdx.x & 31, ty = threadIdx.x >> 5;
#pragma unroll
    for (int i = 0; i < 32; i += 8)
        t[ty + i][tx] = in[(long)(r0 + ty + i) * ldin + c0 + tx];
    __syncthreads();
#pragma unroll
    for (int i = 0; i < 32; i += 8)
        out[(long)(c0 + ty + i) * R + r0 + tx] = __float2half_rn(t[tx][ty + i]);
}

__global__ __launch_bounds__(256) void tconvhh_k(
    const __half* __restrict__ in, __half* __restrict__ out,
    int R, int ldin, long sIn, long sOut)
{
    __shared__ __half t[32][34];
    in  += (long)blockIdx.z * sIn;
    out += (long)blockIdx.z * sOut;
    int r0 = blockIdx.y * 32, c0 = blockIdx.x * 32;
    int tx = threadIdx.x & 31, ty = threadIdx.x >> 5;
#pragma unroll
    for (int i = 0; i < 32; i += 8)
        t[ty + i][tx] = in[(long)(r0 + ty + i) * ldin + c0 + tx];
    __syncthreads();
#pragma unroll
    for (int i = 0; i < 32; i += 8)
        out[(long)(c0 + ty + i) * R + r0 + tx] = t[tx][ty + i];
}

// --------------------- LayerNorm (half output) ------------------------------
template<int MODE>
__global__ __launch_bounds__(256) void ln_k(
    const float* __restrict__ src, const float* __restrict__ res,
    const float* __restrict__ gam, const float* __restrict__ bet,
    __half* __restrict__ out, int c0)
{
    int r = blockIdx.x;
    int b = r >> 9, i = r & 511;
    const float* p = src + ((long)b * S_ + c0 + i) * D_;

    int tid = threadIdx.x;
    float v[4], s = 0.f, sq = 0.f;
#pragma unroll
    for (int k = 0; k < 4; k++) {
        int c = tid + k * 256;
        float xv = p[c];
        if (MODE == 1) xv += res[(long)r * D_ + c];
        v[k] = xv; s += xv; sq += xv * xv;
    }
    __shared__ float shs[8], shq[8];
#pragma unroll
    for (int o = 16; o; o >>= 1) {
        s  += __shfl_xor_sync(0xffffffffu, s,  o);
        sq += __shfl_xor_sync(0xffffffffu, sq, o);
    }
    if ((tid & 31) == 0) { shs[tid >> 5] = s; shq[tid >> 5] = sq; }
    __syncthreads();
    s = 0.f; sq = 0.f;
#pragma unroll
    for (int i2 = 0; i2 < 8; i2++) { s += shs[i2]; sq += shq[i2]; }
    float m  = s * (1.f / D_);
    float var = sq * (1.f / D_) - m * m;
    float rs = rsqrtf(var + 1e-5f);
#pragma unroll
    for (int k = 0; k < 4; k++) {
        int c = tid + k * 256;
        out[(long)r * D_ + c] = __float2half_rn((v[k] - m) * rs * gam[c] + bet[c]);
    }
}

// ------------- combine + LayerNorm3 fused (o fp32, h3 half) -----------------
__global__ __launch_bounds__(256) void cln_k(
    const float* __restrict__ x, const float* __restrict__ gt,
    const float* __restrict__ ao, const float* __restrict__ mc,
    float* __restrict__ o, __half* __restrict__ h3,
    const float* __restrict__ gam, const float* __restrict__ bet, int c0)
{
    int r = blockIdx.x;
    int b = r >> 9, i = r & 511;
    int tid = threadIdx.x;
    float v[4], s = 0.f, sq = 0.f;
#pragma unroll
    for (int k = 0; k < 4; k++) {
        int c = tid + k * 256;
        float xv = x[((long)b * S_ + c0 + i) * D_ + c];
        float gv = gt[(long)r * D_ + c];
        float val = xv + gv * ao[(long)r * D_ + c] + (1.f - gv) * mc[(long)r * D_ + c];
        o[(long)r * D_ + c] = val;
        v[k] = val; s += val; sq += val * val;
    }
    __shared__ float shs[8], shq[8];
#pragma unroll
    for (int w = 16; w; w >>= 1) {
        s  += __shfl_xor_sync(0xffffffffu, s,  w);
        sq += __shfl_xor_sync(0xffffffffu, sq, w);
    }
    if ((tid & 31) == 0) { shs[tid >> 5] = s; shq[tid >> 5] = sq; }
    __syncthreads();
    s = 0.f; sq = 0.f;
#pragma unroll
    for (int i2 = 0; i2 < 8; i2++) { s += shs[i2]; sq += shq[i2]; }
    float m  = s * (1.f / D_);
    float var = sq * (1.f / D_) - m * m;
    float rs = rsqrtf(var + 1e-5f);
#pragma unroll
    for (int k = 0; k < 4; k++) {
        int c = tid + k * 256;
        h3[(long)r * D_ + c] = __float2half_rn((v[k] - m) * rs * gam[c] + bet[c]);
    }
}

// ----------------- row L2 normalize (half, strided) -------------------------
__global__ __launch_bounds__(256) void rownorm_k(__half* __restrict__ km, int ld)
{
    int r = blockIdx.x, tid = threadIdx.x;
    __half* p = km + (long)r * ld;
    float v[4], sq = 0.f;
#pragma unroll
    for (int k = 0; k < 4; k++) {
        int c = tid + k * 256;
        v[k] = __half2float(p[c]); sq += v[k] * v[k];
    }
    __shared__ float shq[8];
#pragma unroll
    for (int o = 16; o; o >>= 1) sq += __shfl_xor_sync(0xffffffffu, sq, o);
    if ((tid & 31) == 0) shq[tid >> 5] = sq;
    __syncthreads();
    sq = 0.f;
#pragma unroll
    for (int i = 0; i < 8; i++) sq += shq[i];
    float rs = rsqrtf(sq + 1e-6f);
#pragma unroll
    for (int k = 0; k < 4; k++) {
        int c = tid + k * 256;
        p[c] = __float2half_rn(v[k] * rs);
    }
}

// ------------------------- softmax (fp32 -> half probs) ---------------------
__global__ __launch_bounds__(256) void softmax_k(
    const float* __restrict__ sc, __half* __restrict__ scp)
{
    const float* row = sc + (long)blockIdx.x * PCP_;
    __half* orow = scp + (long)blockIdx.x * PCP_;
    int tid = threadIdx.x;
    __shared__ float sh[8];
    float mx = -1e30f;
    for (int c = tid; c < PCP_; c += 256) mx = fmaxf(mx, row[c]);
#pragma unroll
    for (int o = 16; o; o >>= 1) mx = fmaxf(mx, __shfl_xor_sync(0xffffffffu, mx, o));
    if ((tid & 31) == 0) sh[tid >> 5] = mx;
    __syncthreads();
    mx = sh[0];
#pragma unroll
    for (int i = 1; i < 8; i++) mx = fmaxf(mx, sh[i]);
    float s = 0.f, ev[3];
    int idx = 0;
    for (int c = tid; c < PCP_; c += 256, idx++) {
        float e = expf(row[c] - mx);
        ev[idx] = e; s += e;
    }
    __syncthreads();
#pragma unroll
    for (int o = 16; o; o >>= 1) s += __shfl_xor_sync(0xffffffffu, s, o);
    if ((tid & 31) == 0) sh[tid >> 5] = s;
    __syncthreads();
    s = 0.f;
#pragma unroll
    for (int i = 0; i < 8; i++) s += sh[i];
    float inv = 1.f / s;
    idx = 0;
    for (int c = tid; c < PCP_; c += 256, idx++)
        orow[c] = __float2half_rn(ev[idx] * inv);
}

// ------------------------------- elementwise --------------------------------
__global__ void zeroinit_k(float* __restrict__ a, float* __restrict__ b,
                           float* __restrict__ tMf, long nd)
{
    long i = (long)blockIdx.x * 256 + threadIdx.x;
    a[i] = 0.f; b[i] = 0.f;
    if (i < nd / 2) tMf[i] = 0.f;
}

__global__ void fillpkv_k(const float* __restrict__ pk, const float* __restrict__ pv,
                          __half* __restrict__ attn)
{
    int idx = blockIdx.x * 256 + threadIdx.x;
    int bh = idx >> 10, rem = idx & 1023;
    int p = rem >> 6, d = rem & 63;
    int h = bh & 15;
    attn[KB_OFF + ((long)bh * PCP_ + p) * DH_ + d] = __float2half_rn(pk[((long)p * H_ + h) * DH_ + d]);
    attn[VB_OFF + ((long)bh * DH_ + d) * PCP_ + p] = __float2half_rn(pv[((long)p * H_ + h) * DH_ + d]);
}

__global__ void cat3_k(const float* __restrict__ a, const float* __restrict__ b,
                       const float* __restrict__ c, float* __restrict__ out,
                       int na, int nb)
{
    int i = blockIdx.x * 256 + threadIdx.x;
    out[i] = (i < na) ? a[i] : (i < na + nb) ? b[i - na] : c[i - na - nb];
}

__global__ void intl2_k(const float* __restrict__ a, const float* __restrict__ b,
                        float* __restrict__ out)   // out[2j]=a[j], out[2j+1]=b[j]
{
    int j = blockIdx.x * 256 + threadIdx.x;
    out[2 * j] = a[j];
    out[2 * j + 1] = b[j];
}

// ----------- M/S update fused with transposed half tM production ------------
__global__ __launch_bounds__(256) void updtr_k(
    float* __restrict__ M, float* __restrict__ S, const float* __restrict__ grad,
    const float* __restrict__ lr, const float* __restrict__ mom,
    const float* __restrict__ fg, __half* __restrict__ tM)
{
    __shared__ float t[32][33];
    int b = blockIdx.z;
    int r0 = blockIdx.y * 32, c0 = blockIdx.x * 32;
    int tx = threadIdx.x & 31, ty = threadIdx.x >> 5;
    float th = 1.f / (1.f + expf(-lr[0]));
    float et = 1.f / (1.f + expf(-mom[0]));
    float al = 1.f / (1.f + expf(-fg[0]));
#pragma unroll
    for (int i = 0; i < 32; i += 8) {
        long idx = ((long)b * D_ + r0 + ty + i) * D_ + c0 + tx;
        float s = et * S[idx] - th * grad[idx];
        S[idx] = s;
        float m = (1.f - al) * M[idx] + s;
        M[idx] = m;
        t[ty + i][tx] = m;
    }
    __syncthreads();
#pragma unroll
    for (int i = 0; i < 32; i += 8)
        tM[((long)b * D_ + c0 + ty + i) * D_ + r0 + tx] = __float2half_rn(t[tx][ty + i]);
}

// --------------------------------- launch -----------------------------------
extern "C" void kernel_launch(void* const* d_in, const int* in_sizes, int n_in,
                              void* d_out, int out_size)
{
    const float* x     = (const float*)d_in[0];
    const float* g1    = (const float*)d_in[1];
    const float* b1    = (const float*)d_in[2];
    const float* g2    = (const float*)d_in[3];
    const float* b2    = (const float*)d_in[4];
    const float* g3    = (const float*)d_in[5];
    const float* b3    = (const float*)d_in[6];
    const float* Wqm   = (const float*)d_in[7];
    const float* Wkm   = (const float*)d_in[8];
    const float* Wvm   = (const float*)d_in[9];
    const float* lr    = (const float*)d_in[10];
    const float* mom   = (const float*)d_in[11];
    const float* fg    = (const float*)d_in[12];
    const float* Wq    = (const float*)d_in[13];
    const float* bq    = (const float*)d_in[14];
    const float* Wk    = (const float*)d_in[15];
    const float* bk    = (const float*)d_in[16];
    const float* Wv    = (const float*)d_in[17];
    const float* bv    = (const float*)d_in[18];
    const float* Wo    = (const float*)d_in[19];
    const float* bo    = (const float*)d_in[20];
    const float* pk    = (const float*)d_in[21];
    const float* pv    = (const float*)d_in[22];
    const float* Wg    = (const float*)d_in[23];
    const float* bg    = (const float*)d_in[24];
    const float* Wgate = (const float*)d_in[25];
    const float* bgate = (const float*)d_in[26];
    const float* Wup   = (const float*)d_in[27];
    const float* bup   = (const float*)d_in[28];
    const float* Wdown = (const float*)d_in[29];
    const float* bdown = (const float*)d_in[30];
    float* outp = (float*)d_out;

    __half *h1, *qkvm, *h2, *attn, *scp, *atg, *h3, *fs;
    float *mc, *pr, *grad, *Mm, *Sm, *sc, *aogt, *o;
    __half *wmem, *wqkv, *wog, *wgui, *wdown;
    __half *tM, *tkm, *tpr;
    float *bqkv, *bgui, *bog;
    cudaGetSymbolAddress((void**)&h1, g_h1);
    cudaGetSymbolAddress((void**)&qkvm, g_qkvm);
    cudaGetSymbolAddress((void**)&mc, g_mc);
    cudaGetSymbolAddress((void**)&pr, g_pr);
    cudaGetSymbolAddress((void**)&grad, g_grad);
    cudaGetSymbolAddress((void**)&Mm, g_Mst);
    cudaGetSymbolAddress((void**)&Sm, g_Sst);
    cudaGetSymbolAddress((void**)&h2, g_h2);
    cudaGetSymbolAddress((void**)&attn, g_attn);
    cudaGetSymbolAddress((void**)&sc, g_sc);
    cudaGetSymbolAddress((void**)&scp, g_scp);
    cudaGetSymbolAddress((void**)&atg, g_atg);
    cudaGetSymbolAddress((void**)&aogt, g_aogt);
    cudaGetSymbolAddress((void**)&o,  g_o);
    cudaGetSymbolAddress((void**)&h3, g_h3);
    cudaGetSymbolAddress((void**)&fs, g_fs);
    cudaGetSymbolAddress((void**)&wmem, w_mem);
    cudaGetSymbolAddress((void**)&wqkv, w_qkv);
    cudaGetSymbolAddress((void**)&wog, w_og);
    cudaGetSymbolAddress((void**)&wgui, w_gui);
    cudaGetSymbolAddress((void**)&wdown, w_down);
    cudaGetSymbolAddress((void**)&tM,  t_M);
    cudaGetSymbolAddress((void**)&tkm, t_km);
    cudaGetSymbolAddress((void**)&tpr, t_pr);
    cudaGetSymbolAddress((void**)&bqkv, b_qkv);
    cudaGetSymbolAddress((void**)&bgui, b_gui);
    cudaGetSymbolAddress((void**)&bog,  b_og);

    cudaFuncSetAttribute(hmma_k<0>,  cudaFuncAttributeMaxDynamicSharedMemorySize, TM_SMEM);
    cudaFuncSetAttribute(hmma_k<5>,  cudaFuncAttributeMaxDynamicSharedMemorySize, TM_SMEM);
    cudaFuncSetAttribute(hmma_k<9>,  cudaFuncAttributeMaxDynamicSharedMemorySize, TM_SMEM);
    cudaFuncSetAttribute(hmma_k<10>, cudaFuncAttributeMaxDynamicSharedMemorySize, TM_SMEM);
    cudaFuncSetAttribute(hmma_k<12>, cudaFuncAttributeMaxDynamicSharedMemorySize, TM_SMEM);
    cudaFuncSetAttribute(hmma_k<14>, cudaFuncAttributeMaxDynamicSharedMemorySize, TM_SMEM);
    cudaFuncSetAttribute(hmma_k<15>, cudaFuncAttributeMaxDynamicSharedMemorySize, TM_SMEM);
    cudaFuncSetAttribute(attn_sc_k, cudaFuncAttributeMaxDynamicSharedMemorySize, SC_SMEM);
    cudaFuncSetAttribute(attn_av_k, cudaFuncAttributeMaxDynamicSharedMemorySize, AV_SMEM);

    const long ND   = (long)B_ * D_ * D_;
    const long NBD  = (long)BC_ * D_;
    const long sDD  = (long)D_ * D_;
    const long sDC  = (long)D_ * C_;
    const long sCD  = (long)C_ * D_;
    const long sQK  = (long)C_ * 3 * D_;

    zeroinit_k<<<(unsigned)(ND / 256), 256>>>(Mm, Sm, (float*)tM, ND);
    fillpkv_k<<<256, 256>>>(pk, pv, attn);
    cat3_k<<<12, 256>>>(bq, bk, bv, bqkv, D_, D_);
    cat3_k<<<8, 256>>>(bo, bg, bg, bog, D_, D_);
    intl2_k<<<16, 256>>>(bgate, bup, bgui);

    dim3 t256(256);
    tconvfh_k<<<dim3(D_/32,  D_/32, 1), t256>>>(Wqm,   wmem,               D_,  D_,  0, 0);
    tconvfh_k<<<dim3(D_/32,  D_/32, 1), t256>>>(Wkm,   wmem + sDD,         D_,  D_,  0, 0);
    tconvfh_k<<<dim3(D_/32,  D_/32, 1), t256>>>(Wvm,   wmem + 2 * sDD,     D_,  D_,  0, 0);
    tconvfh_k<<<dim3(D_/32,  D_/32, 1), t256>>>(Wq,    wqkv,               D_,  D_,  0, 0);
    tconvfh_k<<<dim3(D_/32,  D_/32, 1), t256>>>(Wk,    wqkv + sDD,         D_,  D_,  0, 0);
    tconvfh_k<<<dim3(D_/32,  D_/32, 1), t256>>>(Wv,    wqkv + 2 * sDD,     D_,  D_,  0, 0);
    tconvfh_k<<<dim3(D_/32,  D_/32, 1), t256>>>(Wo,    wog,                D_,  D_,  0, 0);
    tconvfh_k<<<dim3(D_/32,  D_/32, 1), t256>>>(Wg,    wog + sDD,          D_,  D_,  0, 0);
    // interleaved gate/up: out[(2j+p)*D + k]; R passed as row-stride 2*D
    tconvfh_k<<<dim3(FF_/32, D_/32, 1), t256>>>(Wgate, wgui,               2*D_, FF_, 0, 0);
    tconvfh_k<<<dim3(FF_/32, D_/32, 1), t256>>>(Wup,   wgui + D_,          2*D_, FF_, 0, 0);
    tconvfh_k<<<dim3(D_/32, FF_/32, 1), t256>>>(Wdown, wdown,              FF_, D_,  0, 0);

    for (int t = 0; t < NC_; t++) {
        int c0 = t * C_;
        // --- neural memory ---
        ln_k<0><<<BC_, 256>>>(x, nullptr, g1, b1, h1, c0);
        hmma_k<9><<<dim3(24,16), 256, TM_SMEM>>>(h1, wmem, (float*)qkvm, nullptr, nullptr,
            3*D_, D_, D_, 0, 0, 0, 1.f, 0);
        rownorm_k<<<BC_, 256>>>(qkvm + D_, 3*D_);
        hmma_k<15><<<dim3(8,4,8), 256, TM_SMEM>>>(nullptr, nullptr, nullptr, nullptr, nullptr,
            D_, D_, 3*D_, 0, 0, 0, 1.f, 0);
        tconvhh_k<<<dim3(D_/32, C_/32, B_), t256>>>(qkvm + D_, tkm, C_, 3*D_, sQK, sDC);
        tconvfh_k<<<dim3(D_/32, C_/32, B_), t256>>>(pr, tpr, C_, D_, sCD, sDC);
        hmma_k<0><<<dim3(8,8,B_), 256, TM_SMEM>>>(tkm, tpr, grad, nullptr, nullptr,
            D_, C_, C_, sDC, sDC, sDD, 1.f / C_, 0);
        updtr_k<<<dim3(32,32,B_), 256>>>(Mm, Sm, grad, lr, mom, fg, tM);

        // --- attention with persistent tokens ---
        ln_k<1><<<BC_, 256>>>(x, mc, g2, b2, h2, c0);
        hmma_k<10><<<dim3(24,16), 256, TM_SMEM>>>(h2, wqkv, (float*)attn, bqkv, nullptr,
            0, D_, D_, 0, 0, 0, 1.f, 0);
        attn_sc_k<<<dim3(PCP_/128, C_/128, BH_), 256, SC_SMEM>>>(attn, attn + KB_OFF, sc);
        softmax_k<<<BH_ * C_, 256>>>(sc, scp);
        attn_av_k<<<dim3(C_/128, BH_), 256, AV_SMEM>>>(scp, attn + VB_OFF, atg);
        hmma_k<14><<<dim3(8,16,2), 256, TM_SMEM>>>(atg, wog, aogt, bog, nullptr,
            D_, D_, D_, NBD, sDD, NBD, 1.f, 0);
        cln_k<<<BC_, 256>>>(x, aogt + NBD, aogt, mc, o, h3, g3, b3, c0);

        // --- gated FFN (interleaved gate/up, fused silu) ---
        hmma_k<12><<<dim3(64,16), 256, TM_SMEM>>>(h3, wgui, (float*)fs, bgui, nullptr,
            FF_, D_, D_, 0, 0, 0, 1.f, 0);
        hmma_k<5><<<dim3(8,16), 256, TM_SMEM>>>(fs, wdown, o, bdown, outp,
            D_, FF_, FF_, 0, 0, 0, 1.f, c0);
    }
}

// round 12
// speedup vs baseline: 1.4771x; 1.4771x over previous
#include <cuda_runtime.h>
#include <cuda_fp16.h>
#include <math.h>
#include <stdint.h>

#define D_  1024
#define H_  16
#define DH_ 64
#define P_  16
#define C_  512
#define B_  4
#define S_  4096
#define FF_ 4096
#define NC_ 8
#define BC_ (B_*C_)      /* 2048 */
#define PCP_ 640         /* padded key length (5*128) */
#define BH_ (B_*H_)      /* 64   */

static constexpr long KB_OFF = (long)BH_ * C_ * DH_;
static constexpr long VB_OFF = KB_OFF + (long)BH_ * PCP_ * DH_;
static constexpr long ATTN_SZ = VB_OFF + (long)BH_ * DH_ * PCP_;

// ------------------------- scratch (device globals) -------------------------
__device__ __align__(16) __half g_h1[BC_*D_];
__device__ __align__(16) __half g_qkvm[(long)BC_*3*D_];   // qm|km|vm (half)
__device__ float g_mc[BC_*D_];
__device__ __align__(16) __half g_mch[BC_*D_];
__device__ float g_pr[BC_*D_];
__device__ float g_grad[B_*D_*D_];
__device__ float g_Mst[B_*D_*D_];
__device__ float g_Sst[B_*D_*D_];
__device__ __align__(16) __half g_h2[BC_*D_];
__device__ __align__(16) __half g_attn[(size_t)ATTN_SZ]; // qb | kb | vbT
__device__ float g_sc[(long)BH_*C_*PCP_];
__device__ __align__(16) __half g_scp[(long)BH_*C_*PCP_];
__device__ __align__(16) __half g_at[BC_*D_];
__device__ float g_ao[BC_*D_];
__device__ float g_gt[BC_*D_];
__device__ float g_o [BC_*D_];
__device__ __align__(16) __half g_h3[BC_*D_];
__device__ __align__(16) __half g_fs[(long)BC_*FF_];

// half operand buffers ([N,K] K-major for mma B operand)
__device__ __align__(16) __half w_mem[(long)3*D_*D_];
__device__ __align__(16) __half w_qkv[(long)3*D_*D_];
__device__ __align__(16) __half w_o [D_*D_];
__device__ __align__(16) __half w_g [D_*D_];
__device__ __align__(16) __half w_gui[(long)2*FF_*D_];   // interleaved gate/up
__device__ __align__(16) __half w_down[(long)D_*FF_];
__device__ __align__(16) __half t_M [B_*D_*D_];
__device__ __align__(16) __half t_km[(long)B_*D_*C_];
__device__ __align__(16) __half t_pr[(long)B_*D_*C_];
__device__ float b_qkv[3*D_];
__device__ float b_gui[2*FF_];

// ----------------------------- PTX helpers ----------------------------------
__device__ __forceinline__ uint32_t smem_u32(const void* p) {
    uint32_t a;
    asm("{ .reg .u64 t; cvta.to.shared.u64 t, %1; cvt.u32.u64 %0, t; }"
        : "=r"(a) : "l"(p));
    return a;
}
__device__ __forceinline__ void ldsm4(uint32_t& r0, uint32_t& r1, uint32_t& r2,
                                      uint32_t& r3, uint32_t addr) {
    asm volatile("ldmatrix.sync.aligned.m8n8.x4.shared.b16 {%0,%1,%2,%3}, [%4];"
                 : "=r"(r0), "=r"(r1), "=r"(r2), "=r"(r3) : "r"(addr));
}
#define CP_ASYNC16(dst, src)                                                     \
    asm volatile("cp.async.cg.shared.global [%0], [%1], 16;" :: "r"(dst), "l"(src))
#define CP_COMMIT()  asm volatile("cp.async.commit_group;")
#define CP_WAIT(n)   asm volatile("cp.async.wait_group %0;" :: "n"(n))

#define MMAH(d, a, b0, b1)                                                       \
    asm volatile(                                                                \
        "mma.sync.aligned.m16n8k16.row.col.f32.f16.f16.f32 "                     \
        "{%0,%1,%2,%3}, {%4,%5,%6,%7}, {%8,%9}, {%0,%1,%2,%3};"                  \
        : "+f"((d)[0]), "+f"((d)[1]), "+f"((d)[2]), "+f"((d)[3])                 \
        : "r"((a)[0]), "r"((a)[1]), "r"((a)[2]), "r"((a)[3]), "r"(b0), "r"(b1))

// -------------------- FP16 HMMA GEMM, cp.async 3-stage ----------------------
// C = epi(alpha * A[M,K] @ B[N,K]^T). A,B pre-rounded __half. fp32 accum.
// EPI: 0 plain fp32; 1 +bias; 2 sigmoid(+bias); 4 acc - half-aux;
// 5 C+=acc+bias & outp; 9 half store; 10 +bias half qkv-scatter;
// 11 dual fp32 + half; 12 interleaved silu(gate)*up -> half.
#define LDH_ 40
#define HT_ (128 * LDH_)
#define TM_SMEM (3 * 2 * HT_ * 2)   /* 61440 B */

template<int EPI>
__global__ __launch_bounds__(256, 2) void hmma_k(
    const __half* __restrict__ A, const __half* __restrict__ Bw,
    float* __restrict__ Cm, const float* __restrict__ bias,
    void* __restrict__ aux, int ldc, int K, int lda, int ldaux,
    long sA, long sB, long sC, float alpha, int c0)
{
    extern __shared__ __half smh[];
    const int bz = blockIdx.z;
    A  += bz * sA;
    Bw += bz * sB;
    Cm += bz * sC;
    const __half* auxh4  = (EPI == 4)  ? (const __half*)aux + bz * sA : nullptr;
    __half*       auxh11 = (EPI == 11) ? (__half*)aux + bz * sC : nullptr;

    const int tid = threadIdx.x, warp = tid >> 5, lane = tid & 31;
    const int n0 = blockIdx.x * 128, m0 = blockIdx.y * 128;
    const int mo = (warp >> 2) * 64, no = (warp & 3) * 32;
    const int grp = lane >> 2, tig = lane & 3;
    const int lrow = lane & 15, lcol = (lane >> 4) << 3;

    const int lr = tid >> 1;
    const int lc = (tid & 1) << 4;   // halves

    float acc[4][4][4] = {};
    const int KT = K >> 5;

#pragma unroll
    for (int s = 0; s < 2; s++) {
        const int k0 = s << 5;
        __half* As = smh + s * 2 * HT_;
        __half* Bs = As + HT_;
#pragma unroll
        for (int j = 0; j < 2; j++) {
            CP_ASYNC16(smem_u32(&As[lr * LDH_ + lc + 8 * j]), A  + (long)(m0 + lr) * lda + k0 + lc + 8 * j);
            CP_ASYNC16(smem_u32(&Bs[lr * LDH_ + lc + 8 * j]), Bw + (long)(n0 + lr) * K + k0 + lc + 8 * j);
        }
        CP_COMMIT();
    }

    for (int kt = 0; kt < KT; kt++) {
        if (kt + 1 < KT) { CP_WAIT(1); } else { CP_WAIT(0); }
        __syncthreads();

        if (kt + 2 < KT) {
            const int s = (kt + 2) % 3;
            const int k0 = (kt + 2) << 5;
            __half* As = smh + s * 2 * HT_;
            __half* Bs = As + HT_;
#pragma unroll
            for (int j = 0; j < 2; j++) {
                CP_ASYNC16(smem_u32(&As[lr * LDH_ + lc + 8 * j]), A  + (long)(m0 + lr) * lda + k0 + lc + 8 * j);
                CP_ASYNC16(smem_u32(&Bs[lr * LDH_ + lc + 8 * j]), Bw + (long)(n0 + lr) * K + k0 + lc + 8 * j);
            }
            CP_COMMIT();
        }

        const __half* As = smh + (kt % 3) * 2 * HT_;
        const __half* Bs = As + HT_;
        const uint32_t uA = smem_u32(As);
#pragma unroll
        for (int h = 0; h < 2; h++) {
            uint32_t a[4][4], q[8];
#pragma unroll
            for (int mt = 0; mt < 4; mt++) {
                uint32_t ad = uA + (uint32_t)(((mo + mt * 16 + lrow) * LDH_ + h * 16 + lcol) * 2);
                ldsm4(a[mt][0], a[mt][1], a[mt][2], a[mt][3], ad);
            }
#pragma unroll
            for (int g = 0; g < 2; g++) {
                uint32_t bd = smem_u32(&Bs[(no + g * 16 + lrow) * LDH_ + h * 16 + lcol]);
                ldsm4(q[g * 4 + 0], q[g * 4 + 1], q[g * 4 + 2], q[g * 4 + 3], bd);
            }
#pragma unroll
            for (int mt = 0; mt < 4; mt++)
#pragma unroll
                for (int j = 0; j < 4; j++) {
                    uint32_t b0 = q[(j >> 1) * 4 + (j & 1)];
                    uint32_t b1 = q[(j >> 1) * 4 + (j & 1) + 2];
                    MMAH(acc[mt][j], a[mt], b0, b1);
                }
        }
    }

    // ------------------------------ epilogue --------------------------------
#pragma unroll
    for (int mt = 0; mt < 4; mt++) {
#pragma unroll
        for (int j = 0; j < 4; j++) {
            int row = m0 + mo + mt * 16 + grp;
            int col = n0 + no + j * 8 + tig * 2;
#pragma unroll
            for (int hh = 0; hh < 2; hh++) {
                int r = row + hh * 8;
                float v0 = acc[mt][j][hh * 2 + 0] * alpha;
                float v1 = acc[mt][j][hh * 2 + 1] * alpha;
                if (EPI == 1 || EPI == 2 || EPI == 5 || EPI == 10 || EPI == 12) {
                    float2 bv = *(const float2*)(bias + col);
                    v0 += bv.x; v1 += bv.y;
                }
                if (EPI == 9) {
                    __half* Ch = (__half*)Cm;
                    *(__half2*)(Ch + (long)r * ldc + col) = __floats2half2_rn(v0, v1);
                } else if (EPI == 10) {
                    __half* Ch = (__half*)Cm;
                    int b = r >> 9, i = r & 511;
                    int seg = col >> 10, cl = col & 1023;
                    int h = cl >> 6, d = cl & 63;
                    __half2 o = __floats2half2_rn(v0, v1);
                    if (seg == 0)
                        *(__half2*)(Ch + ((((long)b * H_ + h) * C_ + i) * DH_ + d)) = o;
                    else if (seg == 1)
                        *(__half2*)(Ch + KB_OFF + ((((long)b * H_ + h) * PCP_ + P_ + i) * DH_ + d)) = o;
                    else {
                        Ch[VB_OFF + (((long)b * H_ + h) * DH_ + d)     * PCP_ + P_ + i] = __float2half_rn(v0);
                        Ch[VB_OFF + (((long)b * H_ + h) * DH_ + d + 1) * PCP_ + P_ + i] = __float2half_rn(v1);
                    }
                } else if (EPI == 12) {
                    // v0 = gate_j, v1 = up_j (interleaved weight rows)
                    float sg = v0 / (1.f + expf(-v0));
                    ((__half*)Cm)[(long)r * ldc + (col >> 1)] = __float2half_rn(sg * v1);
                } else {
                    float* cp = Cm + (long)r * ldc + col;
                    if (EPI == 2) {
                        v0 = 1.f / (1.f + expf(-v0));
                        v1 = 1.f / (1.f + expf(-v1));
                    }
                    if (EPI == 5) {
                        float2 c = *(float2*)cp;
                        v0 += c.x; v1 += c.y;
                    }
                    if (EPI == 4) {
                        float2 av = __half22float2(*(const __half2*)(auxh4 + (long)r * ldaux + col));
                        v0 -= av.x; v1 -= av.y;
                    }
                    float2 o; o.x = v0; o.y = v1;
                    *(float2*)cp = o;
                    if (EPI == 5) {
                        int b = r >> 9, i = r & 511;
                        *(float2*)((float*)aux + ((long)b * S_ + c0 + i) * D_ + col) = o;
                    }
                    if (EPI == 11)
                        *(__half2*)(auxh11 + (long)r * ldc + col) = __floats2half2_rn(v0, v1);
                }
            }
        }
    }
}

// ------------------ attention scores: S = Q @ K^T * 0.125 + mask ------------
#define SC_LD 72
#define SC_SMEM (2 * 128 * SC_LD * 2)   /* 36864 B */
__global__ __launch_bounds__(256, 2) void attn_sc_k(
    const __half* __restrict__ qb, const __half* __restrict__ kb,
    float* __restrict__ sc)
{
    extern __shared__ __half smh[];
    __half* As = smh;
    __half* Bs = smh + 128 * SC_LD;
    const int bh = blockIdx.z;
    const int n0 = blockIdx.x * 128, m0 = blockIdx.y * 128;
    const __half* Aq = qb + (long)bh * C_ * DH_;
    const __half* Bk = kb + (long)bh * PCP_ * DH_;

    const int tid = threadIdx.x, warp = tid >> 5, lane = tid & 31;
    const int mo = (warp >> 2) * 64, no = (warp & 3) * 32;
    const int grp = lane >> 2, tig = lane & 3;
    const int lrow = lane & 15, lcol = (lane >> 4) << 3;
    const int lr = tid >> 1, lc = (tid & 1) << 5;

    float acc[4][4][4] = {};

#pragma unroll
    for (int j = 0; j < 4; j++) {
        CP_ASYNC16(smem_u32(&As[lr * SC_LD + lc + 8 * j]), Aq + (long)(m0 + lr) * DH_ + lc + 8 * j);
        CP_ASYNC16(smem_u32(&Bs[lr * SC_LD + lc + 8 * j]), Bk + (long)(n0 + lr) * DH_ + lc + 8 * j);
    }
    CP_COMMIT();
    CP_WAIT(0);
    __syncthreads();

    const uint32_t uA = smem_u32(As);
#pragma unroll
    for (int h = 0; h < 4; h++) {
        uint32_t a[4][4], q[8];
#pragma unroll
        for (int mt = 0; mt < 4; mt++) {
            uint32_t ad = uA + (uint32_t)(((mo + mt * 16 + lrow) * SC_LD + h * 16 + lcol) * 2);
            ldsm4(a[mt][0], a[mt][1], a[mt][2], a[mt][3], ad);
        }
#pragma unroll
        for (int g = 0; g < 2; g++) {
            uint32_t bd = smem_u32(&Bs[(no + g * 16 + lrow) * SC_LD + h * 16 + lcol]);
            ldsm4(q[g * 4 + 0], q[g * 4 + 1], q[g * 4 + 2], q[g * 4 + 3], bd);
        }
#pragma unroll
        for (int mt = 0; mt < 4; mt++)
#pragma unroll
            for (int j = 0; j < 4; j++) {
                uint32_t b0 = q[(j >> 1) * 4 + (j & 1)];
                uint32_t b1 = q[(j >> 1) * 4 + (j & 1) + 2];
                MMAH(acc[mt][j], a[mt], b0, b1);
            }
    }

#pragma unroll
    for (int mt = 0; mt < 4; mt++) {
#pragma unroll
        for (int j = 0; j < 4; j++) {
            int row = m0 + mo + mt * 16 + grp;
            int col = n0 + no + j * 8 + tig * 2;
#pragma unroll
            for (int hh = 0; hh < 2; hh++) {
                int gi = row + hh * 8;
                float2 o;
                o.x = (col     < P_ || (col     - P_) <= gi) ? acc[mt][j][hh*2+0] * 0.125f : -1e9f;
                o.y = (col + 1 < P_ || (col + 1 - P_) <= gi) ? acc[mt][j][hh*2+1] * 0.125f : -1e9f;
                *(float2*)(sc + ((long)bh * C_ + gi) * PCP_ + col) = o;
            }
        }
    }
}

// ------------------- attention AV: O = P @ V (half) -------------------------
#define AV_AT (128 * LDH_)
#define AV_BT (64 * LDH_)
#define AV_ST (AV_AT + AV_BT)
#define AV_SMEM (3 * AV_ST * 2)
__global__ __launch_bounds__(256, 2) void attn_av_k(
    const __half* __restrict__ scp, const __half* __restrict__ vbT,
    __half* __restrict__ at)
{
    extern __shared__ __half smh[];
    const int bh = blockIdx.y, b = bh >> 4, h = bh & 15;
    const int m0 = blockIdx.x * 128;
    const __half* Ap = scp + ((long)bh * C_ + m0) * PCP_;
    const __half* Bv = vbT + (long)bh * DH_ * PCP_;

    const int tid = threadIdx.x, warp = tid >> 5, lane = tid & 31;
    const int mo = (warp & 3) * 32, no = (warp >> 2) * 32;
    const int grp = lane >> 2, tig = lane & 3;
    const int lrow = lane & 15, lcol = (lane >> 4) << 3;
    const int lra = tid >> 1, lca = (tid & 1) << 4;
    const int lrb = tid >> 2, lcb = (tid & 3) << 3;

    float acc[2][4][4] = {};
    const int KT = PCP_ >> 5;

#pragma unroll
    for (int s = 0; s < 2; s++) {
        const int k0 = s << 5;
        __half* As = smh + s * AV_ST;
        __half* Bs = As + AV_AT;
#pragma unroll
        for (int j = 0; j < 2; j++)
            CP_ASYNC16(smem_u32(&As[lra * LDH_ + lca + 8 * j]), Ap + (long)lra * PCP_ + k0 + lca + 8 * j);
        CP_ASYNC16(smem_u32(&Bs[lrb * LDH_ + lcb]), Bv + (long)lrb * PCP_ + k0 + lcb);
        CP_COMMIT();
    }

    for (int kt = 0; kt < KT; kt++) {
        if (kt + 1 < KT) { CP_WAIT(1); } else { CP_WAIT(0); }
        __syncthreads();
        if (kt + 2 < KT) {
            const int s = (kt + 2) % 3;
            const int k0 = (kt + 2) << 5;
            __half* As = smh + s * AV_ST;
            __half* Bs = As + AV_AT;
#pragma unroll
            for (int j = 0; j < 2; j++)
                CP_ASYNC16(smem_u32(&As[lra * LDH_ + lca + 8 * j]), Ap + (long)lra * PCP_ + k0 + lca + 8 * j);
            CP_ASYNC16(smem_u32(&Bs[lrb * LDH_ + lcb]), Bv + (long)lrb * PCP_ + k0 + lcb);
            CP_COMMIT();
        }

        const __half* As = smh + (kt % 3) * AV_ST;
        const __half* Bs = As + AV_AT;
        const uint32_t uA = smem_u32(As);
#pragma unroll
        for (int h2 = 0; h2 < 2; h2++) {
            uint32_t a[2][4], q[8];
#pragma unroll
            for (int mt = 0; mt < 2; mt++) {
                uint32_t ad = uA + (uint32_t)(((mo + mt * 16 + lrow) * LDH_ + h2 * 16 + lcol) * 2);
                ldsm4(a[mt][0], a[mt][1], a[mt][2], a[mt][3], ad);
            }
#pragma unroll
            for (int g = 0; g < 2; g++) {
                uint32_t bd = smem_u32(&Bs[(no + g * 16 + lrow) * LDH_ + h2 * 16 + lcol]);
                ldsm4(q[g * 4 + 0], q[g * 4 + 1], q[g * 4 + 2], q[g * 4 + 3], bd);
            }
#pragma unroll
            for (int mt = 0; mt < 2; mt++)
#pragma unroll
                for (int j = 0; j < 4; j++) {
                    uint32_t b0 = q[(j >> 1) * 4 + (j & 1)];
                    uint32_t b1 = q[(j >> 1) * 4 + (j & 1) + 2];
                    MMAH(acc[mt][j], a[mt], b0, b1);
                }
        }
    }

#pragma unroll
    for (int mt = 0; mt < 2; mt++) {
#pragma unroll
        for (int j = 0; j < 4; j++) {
            int row = m0 + mo + mt * 16 + grp;
            int col = no + j * 8 + tig * 2;
#pragma unroll
            for (int hh = 0; hh < 2; hh++) {
                int gi = row + hh * 8;
                *(__half2*)(at + ((long)b * C_ + gi) * D_ + h * DH_ + col) =
                    __floats2half2_rn(acc[mt][j][hh * 2 + 0], acc[mt][j][hh * 2 + 1]);
            }
        }
    }
}

// ------------------- transpose converts -------------------------------------
__global__ __launch_bounds__(256) void tconvfh_k(
    const float* __restrict__ in, __half* __restrict__ out,
    int R, int ldin, long sIn, long sOut)
{
    __shared__ float t[32][33];
    in  += (long)blockIdx.z * sIn;
    out += (long)blockIdx.z * sOut;
    int r0 = blockIdx.y * 32, c0 = blockIdx.x * 32;
    int tx = threadIdx.x & 31, ty = threadIdx.x >> 5;
#pragma unroll
    for (int i = 0; i < 32; i += 8)
        t[ty + i][tx] = in[(long)(r0 + ty + i) * ldin + c0 + tx];
    __syncthreads();
#pragma unroll
    for (int i = 0; i < 32; i += 8)
        out[(long)(c0 + ty + i) * R + r0 + tx] = __float2half_rn(t[tx][ty + i]);
}

__global__ __launch_bounds__(256) void tconvhh_k(
    const __half* __restrict__ in, __half* __restrict__ out,
    int R, int ldin, long sIn, long sOut)
{
    __shared__ __half t[32][34];
    in  += (long)blockIdx.z * sIn;
    out += (long)blockIdx.z * sOut;
    int r0 = blockIdx.y * 32, c0 = blockIdx.x * 32;
    int tx = threadIdx.x & 31, ty = threadIdx.x >> 5;
#pragma unroll
    for (int i = 0; i < 32; i += 8)
        t[ty + i][tx] = in[(long)(r0 + ty + i) * ldin + c0 + tx];
    __syncthreads();
#pragma unroll
    for (int i = 0; i < 32; i += 8)
        out[(long)(c0 + ty + i) * R + r0 + tx] = t[tx][ty + i];
}

// --------------------- LayerNorm (half output) ------------------------------
template<int MODE>
__global__ __launch_bounds__(256) void ln_k(
    const float* __restrict__ src, const float* __restrict__ res,
    const float* __restrict__ gam, const float* __restrict__ bet,
    __half* __restrict__ out, int c0)
{
    int r = blockIdx.x;
    int b = r >> 9, i = r & 511;
    const float* p = src + ((long)b * S_ + c0 + i) * D_;

    int tid = threadIdx.x;
    float v[4], s = 0.f, sq = 0.f;
#pragma unroll
    for (int k = 0; k < 4; k++) {
        int c = tid + k * 256;
        float xv = p[c];
        if (MODE == 1) xv += res[(long)r * D_ + c];
        v[k] = xv; s += xv; sq += xv * xv;
    }
    __shared__ float shs[8], shq[8];
#pragma unroll
    for (int o = 16; o; o >>= 1) {
        s  += __shfl_xor_sync(0xffffffffu, s,  o);
        sq += __shfl_xor_sync(0xffffffffu, sq, o);
    }
    if ((tid & 31) == 0) { shs[tid >> 5] = s; shq[tid >> 5] = sq; }
    __syncthreads();
    s = 0.f; sq = 0.f;
#pragma unroll
    for (int i2 = 0; i2 < 8; i2++) { s += shs[i2]; sq += shq[i2]; }
    float m  = s * (1.f / D_);
    float var = sq * (1.f / D_) - m * m;
    float rs = rsqrtf(var + 1e-5f);
#pragma unroll
    for (int k = 0; k < 4; k++) {
        int c = tid + k * 256;
        out[(long)r * D_ + c] = __float2half_rn((v[k] - m) * rs * gam[c] + bet[c]);
    }
}

// ------------- combine + LayerNorm3 fused (o fp32, h3 half) -----------------
__global__ __launch_bounds__(256) void cln_k(
    const float* __restrict__ x, const float* __restrict__ gt,
    const float* __restrict__ ao, const float* __restrict__ mc,
    float* __restrict__ o, __half* __restrict__ h3,
    const float* __restrict__ gam, const float* __restrict__ bet, int c0)
{
    int r = blockIdx.x;
    int b = r >> 9, i = r & 511;
    int tid = threadIdx.x;
    float v[4], s = 0.f, sq = 0.f;
#pragma unroll
    for (int k = 0; k < 4; k++) {
        int c = tid + k * 256;
        float xv = x[((long)b * S_ + c0 + i) * D_ + c];
        float gv = gt[(long)r * D_ + c];
        float val = xv + gv * ao[(long)r * D_ + c] + (1.f - gv) * mc[(long)r * D_ + c];
        o[(long)r * D_ + c] = val;
        v[k] = val; s += val; sq += val * val;
    }
    __shared__ float shs[8], shq[8];
#pragma unroll
    for (int w = 16; w; w >>= 1) {
        s  += __shfl_xor_sync(0xffffffffu, s,  w);
        sq += __shfl_xor_sync(0xffffffffu, sq, w);
    }
    if ((tid & 31) == 0) { shs[tid >> 5] = s; shq[tid >> 5] = sq; }
    __syncthreads();
    s = 0.f; sq = 0.f;
#pragma unroll
    for (int i2 = 0; i2 < 8; i2++) { s += shs[i2]; sq += shq[i2]; }
    float m  = s * (1.f / D_);
    float var = sq * (1.f / D_) - m * m;
    float rs = rsqrtf(var + 1e-5f);
#pragma unroll
    for (int k = 0; k < 4; k++) {
        int c = tid + k * 256;
        h3[(long)r * D_ + c] = __float2half_rn((v[k] - m) * rs * gam[c] + bet[c]);
    }
}

// ----------------- row L2 normalize (half, strided) -------------------------
__global__ __launch_bounds__(256) void rownorm_k(__half* __restrict__ km, int ld)
{
    int r = blockIdx.x, tid = threadIdx.x;
    __half* p = km + (long)r * ld;
    float v[4], sq = 0.f;
#pragma unroll
    for (int k = 0; k < 4; k++) {
        int c = tid + k * 256;
        v[k] = __half2float(p[c]); sq += v[k] * v[k];
    }
    __shared__ float shq[8];
#pragma unroll
    for (int o = 16; o; o >>= 1) sq += __shfl_xor_sync(0xffffffffu, sq, o);
    if ((tid & 31) == 0) shq[tid >> 5] = sq;
    __syncthreads();
    sq = 0.f;
#pragma unroll
    for (int i = 0; i < 8; i++) sq += shq[i];
    float rs = rsqrtf(sq + 1e-6f);
#pragma unroll
    for (int k = 0; k < 4; k++) {
        int c = tid + k * 256;
        p[c] = __float2half_rn(v[k] * rs);
    }
}

// ------------------------- softmax (fp32 -> half probs) ---------------------
__global__ __launch_bounds__(256) void softmax_k(
    const float* __restrict__ sc, __half* __restrict__ scp)
{
    const float* row = sc + (long)blockIdx.x * PCP_;
    __half* orow = scp + (long)blockIdx.x * PCP_;
    int tid = threadIdx.x;
    __shared__ float sh[8];
    float mx = -1e30f;
    for (int c = tid; c < PCP_; c += 256) mx = fmaxf(mx, row[c]);
#pragma unroll
    for (int o = 16; o; o >>= 1) mx = fmaxf(mx, __shfl_xor_sync(0xffffffffu, mx, o));
    if ((tid & 31) == 0) sh[tid >> 5] = mx;
    __syncthreads();
    mx = sh[0];
#pragma unroll
    for (int i = 1; i < 8; i++) mx = fmaxf(mx, sh[i]);
    float s = 0.f, ev[3];
    int idx = 0;
    for (int c = tid; c < PCP_; c += 256, idx++) {
        float e = expf(row[c] - mx);
        ev[idx] = e; s += e;
    }
    __syncthreads();
#pragma unroll
    for (int o = 16; o; o >>= 1) s += __shfl_xor_sync(0xffffffffu, s, o);
    if ((tid & 31) == 0) sh[tid >> 5] = s;
    __syncthreads();
    s = 0.f;
#pragma unroll
    for (int i = 0; i < 8; i++) s += sh[i];
    float inv = 1.f / s;
    idx = 0;
    for (int c = tid; c < PCP_; c += 256, idx++)
        orow[c] = __float2half_rn(ev[idx] * inv);
}

// ------------------------------- elementwise --------------------------------
__global__ void zeroinit_k(float* __restrict__ a, float* __restrict__ b,
                           float* __restrict__ tMf, long nd)
{
    long i = (long)blockIdx.x * 256 + threadIdx.x;
    a[i] = 0.f; b[i] = 0.f;
    if (i < nd / 2) tMf[i] = 0.f;
}

__global__ void fillpkv_k(const float* __restrict__ pk, const float* __restrict__ pv,
                          __half* __restrict__ attn)
{
    int idx = blockIdx.x * 256 + threadIdx.x;
    int bh = idx >> 10, rem = idx & 1023;
    int p = rem >> 6, d = rem & 63;
    int h = bh & 15;
    attn[KB_OFF + ((long)bh * PCP_ + p) * DH_ + d] = __float2half_rn(pk[((long)p * H_ + h) * DH_ + d]);
    attn[VB_OFF + ((long)bh * DH_ + d) * PCP_ + p] = __float2half_rn(pv[((long)p * H_ + h) * DH_ + d]);
}

__global__ void cat3_k(const float* __restrict__ a, const float* __restrict__ b,
                       const float* __restrict__ c, float* __restrict__ out,
                       int na, int nb)
{
    int i = blockIdx.x * 256 + threadIdx.x;
    out[i] = (i < na) ? a[i] : (i < na + nb) ? b[i - na] : c[i - na - nb];
}

__global__ void intl2_k(const float* __restrict__ a, const float* __restrict__ b,
                        float* __restrict__ out)   // out[2j]=a[j], out[2j+1]=b[j]
{
    int j = blockIdx.x * 256 + threadIdx.x;
    out[2 * j] = a[j];
    out[2 * j + 1] = b[j];
}

// ----------- M/S update fused with transposed half tM production ------------
__global__ __launch_bounds__(256) void updtr_k(
    float* __restrict__ M, float* __restrict__ S, const float* __restrict__ grad,
    const float* __restrict__ lr, const float* __restrict__ mom,
    const float* __restrict__ fg, __half* __restrict__ tM)
{
    __shared__ float t[32][33];
    int b = blockIdx.z;
    int r0 = blockIdx.y * 32, c0 = blockIdx.x * 32;
    int tx = threadIdx.x & 31, ty = threadIdx.x >> 5;
    float th = 1.f / (1.f + expf(-lr[0]));
    float et = 1.f / (1.f + expf(-mom[0]));
    float al = 1.f / (1.f + expf(-fg[0]));
#pragma unroll
    for (int i = 0; i < 32; i += 8) {
        long idx = ((long)b * D_ + r0 + ty + i) * D_ + c0 + tx;
        float s = et * S[idx] - th * grad[idx];
        S[idx] = s;
        float m = (1.f - al) * M[idx] + s;
        M[idx] = m;
        t[ty + i][tx] = m;
    }
    __syncthreads();
#pragma unroll
    for (int i = 0; i < 32; i += 8)
        tM[((long)b * D_ + c0 + ty + i) * D_ + r0 + tx] = __float2half_rn(t[tx][ty + i]);
}

// --------------------------------- launch -----------------------------------
extern "C" void kernel_launch(void* const* d_in, const int* in_sizes, int n_in,
                              void* d_out, int out_size)
{
    const float* x     = (const float*)d_in[0];
    const float* g1    = (const float*)d_in[1];
    const float* b1    = (const float*)d_in[2];
    const float* g2    = (const float*)d_in[3];
    const float* b2    = (const float*)d_in[4];
    const float* g3    = (const float*)d_in[5];
    const float* b3    = (const float*)d_in[6];
    const float* Wqm   = (const float*)d_in[7];
    const float* Wkm   = (const float*)d_in[8];
    const float* Wvm   = (const float*)d_in[9];
    const float* lr    = (const float*)d_in[10];
    const float* mom   = (const float*)d_in[11];
    const float* fg    = (const float*)d_in[12];
    const float* Wq    = (const float*)d_in[13];
    const float* bq    = (const float*)d_in[14];
    const float* Wk    = (const float*)d_in[15];
    const float* bk    = (const float*)d_in[16];
    const float* Wv    = (const float*)d_in[17];
    const float* bv    = (const float*)d_in[18];
    const float* Wo    = (const float*)d_in[19];
    const float* bo    = (const float*)d_in[20];
    const float* pk    = (const float*)d_in[21];
    const float* pv    = (const float*)d_in[22];
    const float* Wg    = (const float*)d_in[23];
    const float* bg    = (const float*)d_in[24];
    const float* Wgate = (const float*)d_in[25];
    const float* bgate = (const float*)d_in[26];
    const float* Wup   = (const float*)d_in[27];
    const float* bup   = (const float*)d_in[28];
    const float* Wdown = (const float*)d_in[29];
    const float* bdown = (const float*)d_in[30];
    float* outp = (float*)d_out;

    __half *h1, *qkvm, *mch, *h2, *attn, *scp, *at, *h3, *fs;
    float *mc, *pr, *grad, *Mm, *Sm, *sc, *ao, *gt, *o;
    __half *wmem, *wqkv, *wo, *wg, *wgui, *wdown;
    __half *tM, *tkm, *tpr;
    float *bqkv, *bgui;
    cudaGetSymbolAddress((void**)&h1, g_h1);
    cudaGetSymbolAddress((void**)&qkvm, g_qkvm);
    cudaGetSymbolAddress((void**)&mc, g_mc);
    cudaGetSymbolAddress((void**)&mch, g_mch);
    cudaGetSymbolAddress((void**)&pr, g_pr);
    cudaGetSymbolAddress((void**)&grad, g_grad);
    cudaGetSymbolAddress((void**)&Mm, g_Mst);
    cudaGetSymbolAddress((void**)&Sm, g_Sst);
    cudaGetSymbolAddress((void**)&h2, g_h2);
    cudaGetSymbolAddress((void**)&attn, g_attn);
    cudaGetSymbolAddress((void**)&sc, g_sc);
    cudaGetSymbolAddress((void**)&scp, g_scp);
    cudaGetSymbolAddress((void**)&at, g_at);
    cudaGetSymbolAddress((void**)&ao, g_ao);
    cudaGetSymbolAddress((void**)&gt, g_gt);
    cudaGetSymbolAddress((void**)&o,  g_o);
    cudaGetSymbolAddress((void**)&h3, g_h3);
    cudaGetSymbolAddress((void**)&fs, g_fs);
    cudaGetSymbolAddress((void**)&wmem, w_mem);
    cudaGetSymbolAddress((void**)&wqkv, w_qkv);
    cudaGetSymbolAddress((void**)&wo,  w_o);
    cudaGetSymbolAddress((void**)&wg,  w_g);
    cudaGetSymbolAddress((void**)&wgui, w_gui);
    cudaGetSymbolAddress((void**)&wdown, w_down);
    cudaGetSymbolAddress((void**)&tM,  t_M);
    cudaGetSymbolAddress((void**)&tkm, t_km);
    cudaGetSymbolAddress((void**)&tpr, t_pr);
    cudaGetSymbolAddress((void**)&bqkv, b_qkv);
    cudaGetSymbolAddress((void**)&bgui, b_gui);

    cudaFuncSetAttribute(hmma_k<0>,  cudaFuncAttributeMaxDynamicSharedMemorySize, TM_SMEM);
    cudaFuncSetAttribute(hmma_k<1>,  cudaFuncAttributeMaxDynamicSharedMemorySize, TM_SMEM);
    cudaFuncSetAttribute(hmma_k<2>,  cudaFuncAttributeMaxDynamicSharedMemorySize, TM_SMEM);
    cudaFuncSetAttribute(hmma_k<4>,  cudaFuncAttributeMaxDynamicSharedMemorySize, TM_SMEM);
    cudaFuncSetAttribute(hmma_k<5>,  cudaFuncAttributeMaxDynamicSharedMemorySize, TM_SMEM);
    cudaFuncSetAttribute(hmma_k<9>,  cudaFuncAttributeMaxDynamicSharedMemorySize, TM_SMEM);
    cudaFuncSetAttribute(hmma_k<10>, cudaFuncAttributeMaxDynamicSharedMemorySize, TM_SMEM);
    cudaFuncSetAttribute(hmma_k<11>, cudaFuncAttributeMaxDynamicSharedMemorySize, TM_SMEM);
    cudaFuncSetAttribute(hmma_k<12>, cudaFuncAttributeMaxDynamicSharedMemorySize, TM_SMEM);
    cudaFuncSetAttribute(attn_sc_k, cudaFuncAttributeMaxDynamicSharedMemorySize, SC_SMEM);
    cudaFuncSetAttribute(attn_av_k, cudaFuncAttributeMaxDynamicSharedMemorySize, AV_SMEM);

    const long ND   = (long)B_ * D_ * D_;
    const long sQK  = (long)C_ * 3 * D_;
    const long sDD  = (long)D_ * D_;
    const long sDC  = (long)D_ * C_;
    const long sCD  = (long)C_ * D_;

    zeroinit_k<<<(unsigned)(ND / 256), 256>>>(Mm, Sm, (float*)tM, ND);
    fillpkv_k<<<256, 256>>>(pk, pv, attn);
    cat3_k<<<12, 256>>>(bq, bk, bv, bqkv, D_, D_);
    intl2_k<<<16, 256>>>(bgate, bup, bgui);

    dim3 t256(256);
    tconvfh_k<<<dim3(D_/32,  D_/32, 1), t256>>>(Wqm,   wmem,               D_,  D_,  0, 0);
    tconvfh_k<<<dim3(D_/32,  D_/32, 1), t256>>>(Wkm,   wmem + sDD,         D_,  D_,  0, 0);
    tconvfh_k<<<dim3(D_/32,  D_/32, 1), t256>>>(Wvm,   wmem + 2 * sDD,     D_,  D_,  0, 0);
    tconvfh_k<<<dim3(D_/32,  D_/32, 1), t256>>>(Wq,    wqkv,               D_,  D_,  0, 0);
    tconvfh_k<<<dim3(D_/32,  D_/32, 1), t256>>>(Wk,    wqkv + sDD,         D_,  D_,  0, 0);
    tconvfh_k<<<dim3(D_/32,  D_/32, 1), t256>>>(Wv,    wqkv + 2 * sDD,     D_,  D_,  0, 0);
    tconvfh_k<<<dim3(D_/32,  D_/32, 1), t256>>>(Wo,    wo,                 D_,  D_,  0, 0);
    tconvfh_k<<<dim3(D_/32,  D_/32, 1), t256>>>(Wg,    wg,                 D_,  D_,  0, 0);
    // interleaved gate/up: gate row j -> wgui row 2j, up row j -> wgui row 2j+1
    tconvfh_k<<<dim3(FF_/32, D_/32, 1), t256>>>(Wgate, wgui,               2*D_, FF_, 0, 0);
    tconvfh_k<<<dim3(FF_/32, D_/32, 1), t256>>>(Wup,   wgui + D_,          2*D_, FF_, 0, 0);
    tconvfh_k<<<dim3(D_/32, FF_/32, 1), t256>>>(Wdown, wdown,              FF_, D_,  0, 0);

    for (int t = 0; t < NC_; t++) {
        int c0 = t * C_;
        // --- neural memory ---
        ln_k<0><<<BC_, 256>>>(x, nullptr, g1, b1, h1, c0);
        hmma_k<9><<<dim3(24,16), 256, TM_SMEM>>>(h1, wmem, (float*)qkvm, nullptr, nullptr,
            3*D_, D_, D_, 0, 0, 0, 0, 1.f, 0);
        rownorm_k<<<BC_, 256>>>(qkvm + D_, 3*D_);
        hmma_k<11><<<dim3(8,4,B_), 256, TM_SMEM>>>(qkvm, tM, mc, nullptr, mch,
            D_, D_, 3*D_, 0, sQK, sDD, sCD, 1.f, 0);
        hmma_k<4><<<dim3(8,4,B_), 256, TM_SMEM>>>(qkvm + D_, tM, pr, nullptr, qkvm + 2*D_,
            D_, D_, 3*D_, 3*D_, sQK, sDD, sCD, 1.f, 0);
        tconvhh_k<<<dim3(D_/32, C_/32, B_), t256>>>(qkvm + D_, tkm, C_, 3*D_, sQK, sDC);
        tconvfh_k<<<dim3(D_/32, C_/32, B_), t256>>>(pr, tpr, C_, D_, sCD, sDC);
        hmma_k<0><<<dim3(8,8,B_), 256, TM_SMEM>>>(tkm, tpr, grad, nullptr, nullptr,
            D_, C_, C_, 0, sDC, sDC, sDD, 1.f / C_, 0);
        updtr_k<<<dim3(32,32,B_), 256>>>(Mm, Sm, grad, lr, mom, fg, tM);

        // --- attention with persistent tokens ---
        ln_k<1><<<BC_, 256>>>(x, mc, g2, b2, h2, c0);
        hmma_k<10><<<dim3(24,16), 256, TM_SMEM>>>(h2, wqkv, (float*)attn, bqkv, nullptr,
            0, D_, D_, 0, 0, 0, 0, 1.f, 0);
        attn_sc_k<<<dim3(PCP_/128, C_/128, BH_), 256, SC_SMEM>>>(attn, attn + KB_OFF, sc);
        softmax_k<<<BH_ * C_, 256>>>(sc, scp);
        attn_av_k<<<dim3(C_/128, BH_), 256, AV_SMEM>>>(scp, attn + VB_OFF, at);
        hmma_k<1><<<dim3(8,16), 256, TM_SMEM>>>(at, wo, ao, bo, nullptr,
            D_, D_, D_, 0, 0, 0, 0, 1.f, 0);
        hmma_k<2><<<dim3(8,16), 256, TM_SMEM>>>(mch, wg, gt, bg, nullptr,
            D_, D_, D_, 0, 0, 0, 0, 1.f, 0);
        cln_k<<<BC_, 256>>>(x, gt, ao, mc, o, h3, g3, b3, c0);

        // --- gated FFN (interleaved gate/up, fused silu) ---
        hmma_k<12><<<dim3(64,16), 256, TM_SMEM>>>(h3, wgui, (float*)fs, bgui, nullptr,
            FF_, D_, D_, 0, 0, 0, 0, 1.f, 0);
        hmma_k<5><<<dim3(8,16), 256, TM_SMEM>>>(fs, wdown, o, bdown, outp,
            D_, FF_, FF_, 0, 0, 0, 0, 1.f, c0);
    }
}

// round 16
// speedup vs baseline: 1.6324x; 1.1051x over previous
#include <cuda_runtime.h>
#include <cuda_fp16.h>
#include <math.h>
#include <stdint.h>

#define D_  1024
#define H_  16
#define DH_ 64
#define P_  16
#define C_  512
#define B_  4
#define S_  4096
#define FF_ 4096
#define NC_ 8
#define BC_ (B_*C_)      /* 2048 */
#define PCP_ 640         /* padded key length (5*128) */
#define BH_ (B_*H_)      /* 64   */

static constexpr long KB_OFF = (long)BH_ * C_ * DH_;
static constexpr long VB_OFF = KB_OFF + (long)BH_ * PCP_ * DH_;
static constexpr long ATTN_SZ = VB_OFF + (long)BH_ * DH_ * PCP_;

// ------------------------- scratch (device globals) -------------------------
__device__ __align__(16) __half g_h1[BC_*D_];
__device__ __align__(16) __half g_qkvm[(long)BC_*3*D_];   // qm|km|vm (half)
__device__ float g_mc[BC_*D_];
__device__ __align__(16) __half g_mch[BC_*D_];
__device__ float g_pr[BC_*D_];
__device__ float g_grad[B_*D_*D_];
__device__ float g_Mst[B_*D_*D_];
__device__ float g_Sst[B_*D_*D_];
__device__ __align__(16) __half g_h2[BC_*D_];
__device__ __align__(16) __half g_attn[(size_t)ATTN_SZ]; // qb | kb | vbT (zero-init pads)
__device__ __align__(16) __half g_at[BC_*D_];
__device__ float g_ao[BC_*D_];
__device__ float g_gt[BC_*D_];
__device__ float g_o [BC_*D_];
__device__ __align__(16) __half g_h3[BC_*D_];
__device__ __align__(16) __half g_fs[(long)BC_*FF_];

// half operand buffers ([N,K] K-major for mma B operand)
__device__ __align__(16) __half w_mem[(long)3*D_*D_];
__device__ __align__(16) __half w_qkv[(long)3*D_*D_];
__device__ __align__(16) __half w_o [D_*D_];
__device__ __align__(16) __half w_g [D_*D_];
__device__ __align__(16) __half w_gui[(long)2*FF_*D_];   // interleaved gate/up
__device__ __align__(16) __half w_down[(long)D_*FF_];
__device__ __align__(16) __half t_M [B_*D_*D_];
__device__ __align__(16) __half t_km[(long)B_*D_*C_];
__device__ __align__(16) __half t_pr[(long)B_*D_*C_];
__device__ float b_qkv[3*D_];
__device__ float b_gui[2*FF_];

// ----------------------------- PTX helpers ----------------------------------
__device__ __forceinline__ uint32_t smem_u32(const void* p) {
    uint32_t a;
    asm("{ .reg .u64 t; cvta.to.shared.u64 t, %1; cvt.u32.u64 %0, t; }"
        : "=r"(a) : "l"(p));
    return a;
}
__device__ __forceinline__ void ldsm4(uint32_t& r0, uint32_t& r1, uint32_t& r2,
                                      uint32_t& r3, uint32_t addr) {
    asm volatile("ldmatrix.sync.aligned.m8n8.x4.shared.b16 {%0,%1,%2,%3}, [%4];"
                 : "=r"(r0), "=r"(r1), "=r"(r2), "=r"(r3) : "r"(addr));
}
#define CP_ASYNC16(dst, src)                                                     \
    asm volatile("cp.async.cg.shared.global [%0], [%1], 16;" :: "r"(dst), "l"(src))
#define CP_COMMIT()  asm volatile("cp.async.commit_group;")
#define CP_WAIT(n)   asm volatile("cp.async.wait_group %0;" :: "n"(n))

#define MMAH(d, a, b0, b1)                                                       \
    asm volatile(                                                                \
        "mma.sync.aligned.m16n8k16.row.col.f32.f16.f16.f32 "                     \
        "{%0,%1,%2,%3}, {%4,%5,%6,%7}, {%8,%9}, {%0,%1,%2,%3};"                  \
        : "+f"((d)[0]), "+f"((d)[1]), "+f"((d)[2]), "+f"((d)[3])                 \
        : "r"((a)[0]), "r"((a)[1]), "r"((a)[2]), "r"((a)[3]), "r"(b0), "r"(b1))

// -------------------- FP16 HMMA GEMM, cp.async 3-stage ----------------------
// C = epi(alpha * A[M,K] @ B[N,K]^T). A,B pre-rounded __half. fp32 accum.
// EPI: 0 plain fp32; 1 +bias; 2 sigmoid(+bias); 4 acc - half-aux;
// 5 C+=acc+bias & outp; 9 half store; 10 +bias half qkv-scatter;
// 11 dual fp32 + half; 12 interleaved silu(gate)*up -> half.
#define LDH_ 40
#define HT_ (128 * LDH_)
#define TM_SMEM (3 * 2 * HT_ * 2)   /* 61440 B */

template<int EPI>
__global__ __launch_bounds__(256, 2) void hmma_k(
    const __half* __restrict__ A, const __half* __restrict__ Bw,
    float* __restrict__ Cm, const float* __restrict__ bias,
    void* __restrict__ aux, int ldc, int K, int lda, int ldaux,
    long sA, long sB, long sC, float alpha, int c0)
{
    extern __shared__ __half smh[];
    const int bz = blockIdx.z;
    A  += bz * sA;
    Bw += bz * sB;
    Cm += bz * sC;
    const __half* auxh4  = (EPI == 4)  ? (const __half*)aux + bz * sA : nullptr;
    __half*       auxh11 = (EPI == 11) ? (__half*)aux + bz * sC : nullptr;

    const int tid = threadIdx.x, warp = tid >> 5, lane = tid & 31;
    const int n0 = blockIdx.x * 128, m0 = blockIdx.y * 128;
    const int mo = (warp >> 2) * 64, no = (warp & 3) * 32;
    const int grp = lane >> 2, tig = lane & 3;
    const int lrow = lane & 15, lcol = (lane >> 4) << 3;

    const int lr = tid >> 1;
    const int lc = (tid & 1) << 4;   // halves

    float acc[4][4][4] = {};
    const int KT = K >> 5;

#pragma unroll
    for (int s = 0; s < 2; s++) {
        const int k0 = s << 5;
        __half* As = smh + s * 2 * HT_;
        __half* Bs = As + HT_;
#pragma unroll
        for (int j = 0; j < 2; j++) {
            CP_ASYNC16(smem_u32(&As[lr * LDH_ + lc + 8 * j]), A  + (long)(m0 + lr) * lda + k0 + lc + 8 * j);
            CP_ASYNC16(smem_u32(&Bs[lr * LDH_ + lc + 8 * j]), Bw + (long)(n0 + lr) * K + k0 + lc + 8 * j);
        }
        CP_COMMIT();
    }

    for (int kt = 0; kt < KT; kt++) {
        if (kt + 1 < KT) { CP_WAIT(1); } else { CP_WAIT(0); }
        __syncthreads();

        if (kt + 2 < KT) {
            const int s = (kt + 2) % 3;
            const int k0 = (kt + 2) << 5;
            __half* As = smh + s * 2 * HT_;
            __half* Bs = As + HT_;
#pragma unroll
            for (int j = 0; j < 2; j++) {
                CP_ASYNC16(smem_u32(&As[lr * LDH_ + lc + 8 * j]), A  + (long)(m0 + lr) * lda + k0 + lc + 8 * j);
                CP_ASYNC16(smem_u32(&Bs[lr * LDH_ + lc + 8 * j]), Bw + (long)(n0 + lr) * K + k0 + lc + 8 * j);
            }
            CP_COMMIT();
        }

        const __half* As = smh + (kt % 3) * 2 * HT_;
        const __half* Bs = As + HT_;
        const uint32_t uA = smem_u32(As);
#pragma unroll
        for (int h = 0; h < 2; h++) {
            uint32_t a[4][4], q[8];
#pragma unroll
            for (int mt = 0; mt < 4; mt++) {
                uint32_t ad = uA + (uint32_t)(((mo + mt * 16 + lrow) * LDH_ + h * 16 + lcol) * 2);
                ldsm4(a[mt][0], a[mt][1], a[mt][2], a[mt][3], ad);
            }
#pragma unroll
            for (int g = 0; g < 2; g++) {
                uint32_t bd = smem_u32(&Bs[(no + g * 16 + lrow) * LDH_ + h * 16 + lcol]);
                ldsm4(q[g * 4 + 0], q[g * 4 + 1], q[g * 4 + 2], q[g * 4 + 3], bd);
            }
#pragma unroll
            for (int mt = 0; mt < 4; mt++)
#pragma unroll
                for (int j = 0; j < 4; j++) {
                    uint32_t b0 = q[(j >> 1) * 4 + (j & 1)];
                    uint32_t b1 = q[(j >> 1) * 4 + (j & 1) + 2];
                    MMAH(acc[mt][j], a[mt], b0, b1);
                }
        }
    }

    // ------------------------------ epilogue --------------------------------
#pragma unroll
    for (int mt = 0; mt < 4; mt++) {
#pragma unroll
        for (int j = 0; j < 4; j++) {
            int row = m0 + mo + mt * 16 + grp;
            int col = n0 + no + j * 8 + tig * 2;
#pragma unroll
            for (int hh = 0; hh < 2; hh++) {
                int r = row + hh * 8;
                float v0 = acc[mt][j][hh * 2 + 0] * alpha;
                float v1 = acc[mt][j][hh * 2 + 1] * alpha;
                if (EPI == 1 || EPI == 2 || EPI == 5 || EPI == 10 || EPI == 12) {
                    float2 bv = *(const float2*)(bias + col);
                    v0 += bv.x; v1 += bv.y;
                }
                if (EPI == 9) {
                    __half* Ch = (__half*)Cm;
                    *(__half2*)(Ch + (long)r * ldc + col) = __floats2half2_rn(v0, v1);
                } else if (EPI == 10) {
                    __half* Ch = (__half*)Cm;
                    int b = r >> 9, i = r & 511;
                    int seg = col >> 10, cl = col & 1023;
                    int h = cl >> 6, d = cl & 63;
                    __half2 o = __floats2half2_rn(v0, v1);
                    if (seg == 0)
                        *(__half2*)(Ch + ((((long)b * H_ + h) * C_ + i) * DH_ + d)) = o;
                    else if (seg == 1)
                        *(__half2*)(Ch + KB_OFF + ((((long)b * H_ + h) * PCP_ + P_ + i) * DH_ + d)) = o;
                    else {
                        Ch[VB_OFF + (((long)b * H_ + h) * DH_ + d)     * PCP_ + P_ + i] = __float2half_rn(v0);
                        Ch[VB_OFF + (((long)b * H_ + h) * DH_ + d + 1) * PCP_ + P_ + i] = __float2half_rn(v1);
                    }
                } else if (EPI == 12) {
                    float sg = v0 / (1.f + expf(-v0));
                    ((__half*)Cm)[(long)r * ldc + (col >> 1)] = __float2half_rn(sg * v1);
                } else {
                    float* cp = Cm + (long)r * ldc + col;
                    if (EPI == 2) {
                        v0 = 1.f / (1.f + expf(-v0));
                        v1 = 1.f / (1.f + expf(-v1));
                    }
                    if (EPI == 5) {
                        float2 c = *(float2*)cp;
                        v0 += c.x; v1 += c.y;
                    }
                    if (EPI == 4) {
                        float2 av = __half22float2(*(const __half2*)(auxh4 + (long)r * ldaux + col));
                        v0 -= av.x; v1 -= av.y;
                    }
                    float2 o; o.x = v0; o.y = v1;
                    *(float2*)cp = o;
                    if (EPI == 5) {
                        int b = r >> 9, i = r & 511;
                        *(float2*)((float*)aux + ((long)b * S_ + c0 + i) * D_ + col) = o;
                    }
                    if (EPI == 11)
                        *(__half2*)(auxh11 + (long)r * ldc + col) = __floats2half2_rn(v0, v1);
                }
            }
        }
    }
}

// ----------------- fused flash attention (scores+softmax+AV) ----------------
// Per CTA: 128 q-rows of one (b,h); online softmax over 5 key-blocks of 128.
#define FQ_LD 72
#define FV_LD 136
#define FA_SMEM ((128*FQ_LD + 2*128*FQ_LD + 2*64*FV_LD) * 2)   /* 90112 B */
__global__ __launch_bounds__(256, 1) void fattn_k(
    const __half* __restrict__ qb, const __half* __restrict__ kbuf,
    const __half* __restrict__ vbT, __half* __restrict__ at)
{
    extern __shared__ __half smh[];
    __half* Qs = smh;                          // 128 x FQ_LD
    __half* Ks = smh + 128 * FQ_LD;            // 2 x 128 x FQ_LD
    __half* Vs = Ks + 2 * 128 * FQ_LD;         // 2 x 64 x FV_LD

    const int bh = blockIdx.y, b = bh >> 4, h = bh & 15;
    const int m0 = blockIdx.x * 128;
    const __half* Q = qb  + ((long)bh * C_ + m0) * DH_;
    const __half* K = kbuf + (long)bh * PCP_ * DH_;
    const __half* V = vbT + (long)bh * DH_ * PCP_;

    const int tid = threadIdx.x, warp = tid >> 5, lane = tid & 31;
    const int grp = lane >> 2, tig = lane & 3;
    const int lrow = lane & 15, lcol = (lane >> 4) << 3;
    const int lrk = tid >> 1, lck = (tid & 1) << 5;   // 128-row loader
    const int lrv = tid >> 2, lcv = (tid & 3) << 5;   // 64-row loader

    // ---- load Q + K0 + V0 ----
#pragma unroll
    for (int j = 0; j < 4; j++)
        CP_ASYNC16(smem_u32(&Qs[lrk * FQ_LD + lck + 8 * j]), Q + (long)lrk * DH_ + lck + 8 * j);
#pragma unroll
    for (int j = 0; j < 4; j++)
        CP_ASYNC16(smem_u32(&Ks[lrk * FQ_LD + lck + 8 * j]), K + (long)lrk * DH_ + lck + 8 * j);
#pragma unroll
    for (int j = 0; j < 4; j++)
        CP_ASYNC16(smem_u32(&Vs[lrv * FV_LD + lcv + 8 * j]), V + (long)lrv * PCP_ + lcv + 8 * j);
    CP_COMMIT();

    float sm0 = -1e30f, sm1 = -1e30f, l0 = 0.f, l1 = 0.f;
    float o[8][4] = {};
    const int gi0 = m0 + warp * 16 + grp, gi1 = gi0 + 8;

    for (int kb = 0; kb < 5; kb++) {
        CP_WAIT(0);
        __syncthreads();
        if (kb + 1 < 5) {
            const int nb = (kb + 1) & 1;
            const int koff = (kb + 1) * 128;
            __half* Kn = Ks + nb * 128 * FQ_LD;
            __half* Vn = Vs + nb * 64 * FV_LD;
#pragma unroll
            for (int j = 0; j < 4; j++)
                CP_ASYNC16(smem_u32(&Kn[lrk * FQ_LD + lck + 8 * j]), K + (long)(koff + lrk) * DH_ + lck + 8 * j);
#pragma unroll
            for (int j = 0; j < 4; j++)
                CP_ASYNC16(smem_u32(&Vn[lrv * FV_LD + lcv + 8 * j]), V + (long)lrv * PCP_ + koff + lcv + 8 * j);
            CP_COMMIT();
        }

        const __half* Kb = Ks + (kb & 1) * 128 * FQ_LD;
        const __half* Vb = Vs + (kb & 1) * 64 * FV_LD;
        const uint32_t uK = smem_u32(Kb), uV = smem_u32(Vb);

        // ---- scores: 16 q-rows x 128 keys per warp ----
        float s[16][4] = {};
#pragma unroll
        for (int h4 = 0; h4 < 4; h4++) {
            uint32_t a[4];
            uint32_t ad = smem_u32(&Qs[(warp * 16 + lrow) * FQ_LD + h4 * 16 + lcol]);
            ldsm4(a[0], a[1], a[2], a[3], ad);
#pragma unroll
            for (int g = 0; g < 8; g++) {
                uint32_t q4[4];
                ldsm4(q4[0], q4[1], q4[2], q4[3],
                      uK + (uint32_t)(((g * 16 + lrow) * FQ_LD + h4 * 16 + lcol) * 2));
                MMAH(s[2 * g],     a, q4[0], q4[2]);
                MMAH(s[2 * g + 1], a, q4[1], q4[3]);
            }
        }

        // ---- mask + scale + row max ----
        float mx0 = -1e30f, mx1 = -1e30f;
#pragma unroll
        for (int j = 0; j < 16; j++) {
            int c0 = kb * 128 + j * 8 + tig * 2, c1 = c0 + 1;
            s[j][0] = (c0 < P_ || c0 - P_ <= gi0) ? s[j][0] * 0.125f : -1e30f;
            s[j][1] = (c1 < P_ || c1 - P_ <= gi0) ? s[j][1] * 0.125f : -1e30f;
            s[j][2] = (c0 < P_ || c0 - P_ <= gi1) ? s[j][2] * 0.125f : -1e30f;
            s[j][3] = (c1 < P_ || c1 - P_ <= gi1) ? s[j][3] * 0.125f : -1e30f;
            mx0 = fmaxf(mx0, fmaxf(s[j][0], s[j][1]));
            mx1 = fmaxf(mx1, fmaxf(s[j][2], s[j][3]));
        }
#pragma unroll
        for (int w = 1; w <= 2; w <<= 1) {
            mx0 = fmaxf(mx0, __shfl_xor_sync(0xffffffffu, mx0, w));
            mx1 = fmaxf(mx1, __shfl_xor_sync(0xffffffffu, mx1, w));
        }
        float mn0 = fmaxf(sm0, mx0), mn1 = fmaxf(sm1, mx1);
        float cr0 = __expf(sm0 - mn0), cr1 = __expf(sm1 - mn1);
        sm0 = mn0; sm1 = mn1;

        // ---- exp, sum, pack probs into AV A-fragments ----
        uint32_t pa[8][4];
        float su0 = 0.f, su1 = 0.f;
#pragma unroll
        for (int j = 0; j < 16; j++) {
            float p0 = __expf(s[j][0] - mn0), p1 = __expf(s[j][1] - mn0);
            float p2 = __expf(s[j][2] - mn1), p3 = __expf(s[j][3] - mn1);
            su0 += p0 + p1; su1 += p2 + p3;
            __half2 h01 = __floats2half2_rn(p0, p1);
            __half2 h23 = __floats2half2_rn(p2, p3);
            int kt = j >> 1, odd = j & 1;
            pa[kt][odd ? 2 : 0] = *(uint32_t*)&h01;
            pa[kt][odd ? 3 : 1] = *(uint32_t*)&h23;
        }
#pragma unroll
        for (int w = 1; w <= 2; w <<= 1) {
            su0 += __shfl_xor_sync(0xffffffffu, su0, w);
            su1 += __shfl_xor_sync(0xffffffffu, su1, w);
        }
        l0 = l0 * cr0 + su0;
        l1 = l1 * cr1 + su1;
#pragma unroll
        for (int nd = 0; nd < 8; nd++) {
            o[nd][0] *= cr0; o[nd][1] *= cr0;
            o[nd][2] *= cr1; o[nd][3] *= cr1;
        }

        // ---- AV: O += P @ V ----
#pragma unroll
        for (int kt = 0; kt < 8; kt++) {
#pragma unroll
            for (int g = 0; g < 4; g++) {
                uint32_t v4[4];
                ldsm4(v4[0], v4[1], v4[2], v4[3],
                      uV + (uint32_t)(((g * 16 + lrow) * FV_LD + kt * 16 + lcol) * 2));
                MMAH(o[2 * g],     pa[kt], v4[0], v4[2]);
                MMAH(o[2 * g + 1], pa[kt], v4[1], v4[3]);
            }
        }
    }

    // ---- writeout ----
    float inv0 = 1.f / l0, inv1 = 1.f / l1;
#pragma unroll
    for (int nd = 0; nd < 8; nd++) {
        int col = h * DH_ + nd * 8 + tig * 2;
        *(__half2*)(at + ((long)b * C_ + gi0) * D_ + col) =
            __floats2half2_rn(o[nd][0] * inv0, o[nd][1] * inv0);
        *(__half2*)(at + ((long)b * C_ + gi1) * D_ + col) =
            __floats2half2_rn(o[nd][2] * inv1, o[nd][3] * inv1);
    }
}

// ------------------- transpose converts -------------------------------------
__global__ __launch_bounds__(256) void tconvfh_k(
    const float* __restrict__ in, __half* __restrict__ out,
    int R, int ldin, long sIn, long sOut)
{
    __shared__ float t[32][33];
    in  += (long)blockIdx.z * sIn;
    out += (long)blockIdx.z * sOut;
    int r0 = blockIdx.y * 32, c0 = blockIdx.x * 32;
    int tx = threadIdx.x & 31, ty = threadIdx.x >> 5;
#pragma unroll
    for (int i = 0; i < 32; i += 8)
        t[ty + i][tx] = in[(long)(r0 + ty + i) * ldin + c0 + tx];
    __syncthreads();
#pragma unroll
    for (int i = 0; i < 32; i += 8)
        out[(long)(c0 + ty + i) * R + r0 + tx] = __float2half_rn(t[tx][ty + i]);
}

__global__ __launch_bounds__(256) void tconvhh_k(
    const __half* __restrict__ in, __half* __restrict__ out,
    int R, int ldin, long sIn, long sOut)
{
    __shared__ __half t[32][34];
    in  += (long)blockIdx.z * sIn;
    out += (long)blockIdx.z * sOut;
    int r0 = blockIdx.y * 32, c0 = blockIdx.x * 32;
    int tx = threadIdx.x & 31, ty = threadIdx.x >> 5;
#pragma unroll
    for (int i = 0; i < 32; i += 8)
        t[ty + i][tx] = in[(long)(r0 + ty + i) * ldin + c0 + tx];
    __syncthreads();
#pragma unroll
    for (int i = 0; i < 32; i += 8)
        out[(long)(c0 + ty + i) * R + r0 + tx] = t[tx][ty + i];
}

// --------------------- LayerNorm (half output) ------------------------------
template<int MODE>
__global__ __launch_bounds__(256) void ln_k(
    const float* __restrict__ src, const float* __restrict__ res,
    const float* __restrict__ gam, const float* __restrict__ bet,
    __half* __restrict__ out, int c0)
{
    int r = blockIdx.x;
    int b = r >> 9, i = r & 511;
    const float* p = src + ((long)b * S_ + c0 + i) * D_;

    int tid = threadIdx.x;
    float v[4], s = 0.f, sq = 0.f;
#pragma unroll
    for (int k = 0; k < 4; k++) {
        int c = tid + k * 256;
        float xv = p[c];
        if (MODE == 1) xv += res[(long)r * D_ + c];
        v[k] = xv; s += xv; sq += xv * xv;
    }
    __shared__ float shs[8], shq[8];
#pragma unroll
    for (int o = 16; o; o >>= 1) {
        s  += __shfl_xor_sync(0xffffffffu, s,  o);
        sq += __shfl_xor_sync(0xffffffffu, sq, o);
    }
    if ((tid & 31) == 0) { shs[tid >> 5] = s; shq[tid >> 5] = sq; }
    __syncthreads();
    s = 0.f; sq = 0.f;
#pragma unroll
    for (int i2 = 0; i2 < 8; i2++) { s += shs[i2]; sq += shq[i2]; }
    float m  = s * (1.f / D_);
    float var = sq * (1.f / D_) - m * m;
    float rs = rsqrtf(var + 1e-5f);
#pragma unroll
    for (int k = 0; k < 4; k++) {
        int c = tid + k * 256;
        out[(long)r * D_ + c] = __float2half_rn((v[k] - m) * rs * gam[c] + bet[c]);
    }
}

// ------------- combine + LayerNorm3 fused (o fp32, h3 half) -----------------
__global__ __launch_bounds__(256) void cln_k(
    const float* __restrict__ x, const float* __restrict__ gt,
    const float* __restrict__ ao, const float* __restrict__ mc,
    float* __restrict__ o, __half* __restrict__ h3,
    const float* __restrict__ gam, const float* __restrict__ bet, int c0)
{
    int r = blockIdx.x;
    int b = r >> 9, i = r & 511;
    int tid = threadIdx.x;
    float v[4], s = 0.f, sq = 0.f;
#pragma unroll
    for (int k = 0; k < 4; k++) {
        int c = tid + k * 256;
        float xv = x[((long)b * S_ + c0 + i) * D_ + c];
        float gv = gt[(long)r * D_ + c];
        float val = xv + gv * ao[(long)r * D_ + c] + (1.f - gv) * mc[(long)r * D_ + c];
        o[(long)r * D_ + c] = val;
        v[k] = val; s += val; sq += val * val;
    }
    __shared__ float shs[8], shq[8];
#pragma unroll
    for (int w = 16; w; w >>= 1) {
        s  += __shfl_xor_sync(0xffffffffu, s,  w);
        sq += __shfl_xor_sync(0xffffffffu, sq, w);
    }
    if ((tid & 31) == 0) { shs[tid >> 5] = s; shq[tid >> 5] = sq; }
    __syncthreads();
    s = 0.f; sq = 0.f;
#pragma unroll
    for (int i2 = 0; i2 < 8; i2++) { s += shs[i2]; sq += shq[i2]; }
    float m  = s * (1.f / D_);
    float var = sq * (1.f / D_) - m * m;
    float rs = rsqrtf(var + 1e-5f);
#pragma unroll
    for (int k = 0; k < 4; k++) {
        int c = tid + k * 256;
        h3[(long)r * D_ + c] = __float2half_rn((v[k] - m) * rs * gam[c] + bet[c]);
    }
}

// ----------------- row L2 normalize (half, strided) -------------------------
__global__ __launch_bounds__(256) void rownorm_k(__half* __restrict__ km, int ld)
{
    int r = blockIdx.x, tid = threadIdx.x;
    __half* p = km + (long)r * ld;
    float v[4], sq = 0.f;
#pragma unroll
    for (int k = 0; k < 4; k++) {
        int c = tid + k * 256;
        v[k] = __half2float(p[c]); sq += v[k] * v[k];
    }
    __shared__ float shq[8];
#pragma unroll
    for (int o = 16; o; o >>= 1) sq += __shfl_xor_sync(0xffffffffu, sq, o);
    if ((tid & 31) == 0) shq[tid >> 5] = sq;
    __syncthreads();
    sq = 0.f;
#pragma unroll
    for (int i = 0; i < 8; i++) sq += shq[i];
    float rs = rsqrtf(sq + 1e-6f);
#pragma unroll
    for (int k = 0; k < 4; k++) {
        int c = tid + k * 256;
        p[c] = __float2half_rn(v[k] * rs);
    }
}

// ------------------------------- elementwise --------------------------------
__global__ void zeroinit_k(float* __restrict__ a, float* __restrict__ b,
                           float* __restrict__ tMf, long nd)
{
    long i = (long)blockIdx.x * 256 + threadIdx.x;
    a[i] = 0.f; b[i] = 0.f;
    if (i < nd / 2) tMf[i] = 0.f;
}

__global__ void fillpkv_k(const float* __restrict__ pk, const float* __restrict__ pv,
                          __half* __restrict__ attn)
{
    int idx = blockIdx.x * 256 + threadIdx.x;
    int bh = idx >> 10, rem = idx & 1023;
    int p = rem >> 6, d = rem & 63;
    int h = bh & 15;
    attn[KB_OFF + ((long)bh * PCP_ + p) * DH_ + d] = __float2half_rn(pk[((long)p * H_ + h) * DH_ + d]);
    attn[VB_OFF + ((long)bh * DH_ + d) * PCP_ + p] = __float2half_rn(pv[((long)p * H_ + h) * DH_ + d]);
}

__global__ void cat3_k(const float* __restrict__ a, const float* __restrict__ b,
                       const float* __restrict__ c, float* __restrict__ out,
                       int na, int nb)
{
    int i = blockIdx.x * 256 + threadIdx.x;
    out[i] = (i < na) ? a[i] : (i < na + nb) ? b[i - na] : c[i - na - nb];
}

__global__ void intl2_k(const float* __restrict__ a, const float* __restrict__ b,
                        float* __restrict__ out)
{
    int j = blockIdx.x * 256 + threadIdx.x;
    out[2 * j] = a[j];
    out[2 * j + 1] = b[j];
}

// ----------- M/S update fused with transposed half tM production ------------
__global__ __launch_bounds__(256) void updtr_k(
    float* __restrict__ M, float* __restrict__ S, const float* __restrict__ grad,
    const float* __restrict__ lr, const float* __restrict__ mom,
    const float* __restrict__ fg, __half* __restrict__ tM)
{
    __shared__ float t[32][33];
    int b = blockIdx.z;
    int r0 = blockIdx.y * 32, c0 = blockIdx.x * 32;
    int tx = threadIdx.x & 31, ty = threadIdx.x >> 5;
    float th = 1.f / (1.f + expf(-lr[0]));
    float et = 1.f / (1.f + expf(-mom[0]));
    float al = 1.f / (1.f + expf(-fg[0]));
#pragma unroll
    for (int i = 0; i < 32; i += 8) {
        long idx = ((long)b * D_ + r0 + ty + i) * D_ + c0 + tx;
        float s = et * S[idx] - th * grad[idx];
        S[idx] = s;
        float m = (1.f - al) * M[idx] + s;
        M[idx] = m;
        t[ty + i][tx] = m;
    }
    __syncthreads();
#pragma unroll
    for (int i = 0; i < 32; i += 8)
        tM[((long)b * D_ + c0 + ty + i) * D_ + r0 + tx] = __float2half_rn(t[tx][ty + i]);
}

// --------------------------------- launch -----------------------------------
extern "C" void kernel_launch(void* const* d_in, const int* in_sizes, int n_in,
                              void* d_out, int out_size)
{
    const float* x     = (const float*)d_in[0];
    const float* g1    = (const float*)d_in[1];
    const float* b1    = (const float*)d_in[2];
    const float* g2    = (const float*)d_in[3];
    const float* b2    = (const float*)d_in[4];
    const float* g3    = (const float*)d_in[5];
    const float* b3    = (const float*)d_in[6];
    const float* Wqm   = (const float*)d_in[7];
    const float* Wkm   = (const float*)d_in[8];
    const float* Wvm   = (const float*)d_in[9];
    const float* lr    = (const float*)d_in[10];
    const float* mom   = (const float*)d_in[11];
    const float* fg    = (const float*)d_in[12];
    const float* Wq    = (const float*)d_in[13];
    const float* bq    = (const float*)d_in[14];
    const float* Wk    = (const float*)d_in[15];
    const float* bk    = (const float*)d_in[16];
    const float* Wv    = (const float*)d_in[17];
    const float* bv    = (const float*)d_in[18];
    const float* Wo    = (const float*)d_in[19];
    const float* bo    = (const float*)d_in[20];
    const float* pk    = (const float*)d_in[21];
    const float* pv    = (const float*)d_in[22];
    const float* Wg    = (const float*)d_in[23];
    const float* bg    = (const float*)d_in[24];
    const float* Wgate = (const float*)d_in[25];
    const float* bgate = (const float*)d_in[26];
    const float* Wup   = (const float*)d_in[27];
    const float* bup   = (const float*)d_in[28];
    const float* Wdown = (const float*)d_in[29];
    const float* bdown = (const float*)d_in[30];
    float* outp = (float*)d_out;

    __half *h1, *qkvm, *mch, *h2, *attn, *at, *h3, *fs;
    float *mc, *pr, *grad, *Mm, *Sm, *ao, *gt, *o;
    __half *wmem, *wqkv, *wo, *wg, *wgui, *wdown;
    __half *tM, *tkm, *tpr;
    float *bqkv, *bgui;
    cudaGetSymbolAddress((void**)&h1, g_h1);
    cudaGetSymbolAddress((void**)&qkvm, g_qkvm);
    cudaGetSymbolAddress((void**)&mc, g_mc);
    cudaGetSymbolAddress((void**)&mch, g_mch);
    cudaGetSymbolAddress((void**)&pr, g_pr);
    cudaGetSymbolAddress((void**)&grad, g_grad);
    cudaGetSymbolAddress((void**)&Mm, g_Mst);
    cudaGetSymbolAddress((void**)&Sm, g_Sst);
    cudaGetSymbolAddress((void**)&h2, g_h2);
    cudaGetSymbolAddress((void**)&attn, g_attn);
    cudaGetSymbolAddress((void**)&at, g_at);
    cudaGetSymbolAddress((void**)&ao, g_ao);
    cudaGetSymbolAddress((void**)&gt, g_gt);
    cudaGetSymbolAddress((void**)&o,  g_o);
    cudaGetSymbolAddress((void**)&h3, g_h3);
    cudaGetSymbolAddress((void**)&fs, g_fs);
    cudaGetSymbolAddress((void**)&wmem, w_mem);
    cudaGetSymbolAddress((void**)&wqkv, w_qkv);
    cudaGetSymbolAddress((void**)&wo,  w_o);
    cudaGetSymbolAddress((void**)&wg,  w_g);
    cudaGetSymbolAddress((void**)&wgui, w_gui);
    cudaGetSymbolAddress((void**)&wdown, w_down);
    cudaGetSymbolAddress((void**)&tM,  t_M);
    cudaGetSymbolAddress((void**)&tkm, t_km);
    cudaGetSymbolAddress((void**)&tpr, t_pr);
    cudaGetSymbolAddress((void**)&bqkv, b_qkv);
    cudaGetSymbolAddress((void**)&bgui, b_gui);

    cudaFuncSetAttribute(hmma_k<0>,  cudaFuncAttributeMaxDynamicSharedMemorySize, TM_SMEM);
    cudaFuncSetAttribute(hmma_k<1>,  cudaFuncAttributeMaxDynamicSharedMemorySize, TM_SMEM);
    cudaFuncSetAttribute(hmma_k<2>,  cudaFuncAttributeMaxDynamicSharedMemorySize, TM_SMEM);
    cudaFuncSetAttribute(hmma_k<4>,  cudaFuncAttributeMaxDynamicSharedMemorySize, TM_SMEM);
    cudaFuncSetAttribute(hmma_k<5>,  cudaFuncAttributeMaxDynamicSharedMemorySize, TM_SMEM);
    cudaFuncSetAttribute(hmma_k<9>,  cudaFuncAttributeMaxDynamicSharedMemorySize, TM_SMEM);
    cudaFuncSetAttribute(hmma_k<10>, cudaFuncAttributeMaxDynamicSharedMemorySize, TM_SMEM);
    cudaFuncSetAttribute(hmma_k<11>, cudaFuncAttributeMaxDynamicSharedMemorySize, TM_SMEM);
    cudaFuncSetAttribute(hmma_k<12>, cudaFuncAttributeMaxDynamicSharedMemorySize, TM_SMEM);
    cudaFuncSetAttribute(fattn_k, cudaFuncAttributeMaxDynamicSharedMemorySize, FA_SMEM);

    const long ND   = (long)B_ * D_ * D_;
    const long sQK  = (long)C_ * 3 * D_;
    const long sDD  = (long)D_ * D_;
    const long sDC  = (long)D_ * C_;
    const long sCD  = (long)C_ * D_;

    zeroinit_k<<<(unsigned)(ND / 256), 256>>>(Mm, Sm, (float*)tM, ND);
    fillpkv_k<<<256, 256>>>(pk, pv, attn);
    cat3_k<<<12, 256>>>(bq, bk, bv, bqkv, D_, D_);
    intl2_k<<<16, 256>>>(bgate, bup, bgui);

    dim3 t256(256);
    tconvfh_k<<<dim3(D_/32,  D_/32, 1), t256>>>(Wqm,   wmem,               D_,  D_,  0, 0);
    tconvfh_k<<<dim3(D_/32,  D_/32, 1), t256>>>(Wkm,   wmem + sDD,         D_,  D_,  0, 0);
    tconvfh_k<<<dim3(D_/32,  D_/32, 1), t256>>>(Wvm,   wmem + 2 * sDD,     D_,  D_,  0, 0);
    tconvfh_k<<<dim3(D_/32,  D_/32, 1), t256>>>(Wq,    wqkv,               D_,  D_,  0, 0);
    tconvfh_k<<<dim3(D_/32,  D_/32, 1), t256>>>(Wk,    wqkv + sDD,         D_,  D_,  0, 0);
    tconvfh_k<<<dim3(D_/32,  D_/32, 1), t256>>>(Wv,    wqkv + 2 * sDD,     D_,  D_,  0, 0);
    tconvfh_k<<<dim3(D_/32,  D_/32, 1), t256>>>(Wo,    wo,                 D_,  D_,  0, 0);
    tconvfh_k<<<dim3(D_/32,  D_/32, 1), t256>>>(Wg,    wg,                 D_,  D_,  0, 0);
    tconvfh_k<<<dim3(FF_/32, D_/32, 1), t256>>>(Wgate, wgui,               2*D_, FF_, 0, 0);
    tconvfh_k<<<dim3(FF_/32, D_/32, 1), t256>>>(Wup,   wgui + D_,          2*D_, FF_, 0, 0);
    tconvfh_k<<<dim3(D_/32, FF_/32, 1), t256>>>(Wdown, wdown,              FF_, D_,  0, 0);

    for (int t = 0; t < NC_; t++) {
        int c0 = t * C_;
        // --- neural memory ---
        ln_k<0><<<BC_, 256>>>(x, nullptr, g1, b1, h1, c0);
        hmma_k<9><<<dim3(24,16), 256, TM_SMEM>>>(h1, wmem, (float*)qkvm, nullptr, nullptr,
            3*D_, D_, D_, 0, 0, 0, 0, 1.f, 0);
        rownorm_k<<<BC_, 256>>>(qkvm + D_, 3*D_);
        hmma_k<11><<<dim3(8,4,B_), 256, TM_SMEM>>>(qkvm, tM, mc, nullptr, mch,
            D_, D_, 3*D_, 0, sQK, sDD, sCD, 1.f, 0);
        hmma_k<4><<<dim3(8,4,B_), 256, TM_SMEM>>>(qkvm + D_, tM, pr, nullptr, qkvm + 2*D_,
            D_, D_, 3*D_, 3*D_, sQK, sDD, sCD, 1.f, 0);
        tconvhh_k<<<dim3(D_/32, C_/32, B_), t256>>>(qkvm + D_, tkm, C_, 3*D_, sQK, sDC);
        tconvfh_k<<<dim3(D_/32, C_/32, B_), t256>>>(pr, tpr, C_, D_, sCD, sDC);
        hmma_k<0><<<dim3(8,8,B_), 256, TM_SMEM>>>(tkm, tpr, grad, nullptr, nullptr,
            D_, C_, C_, 0, sDC, sDC, sDD, 1.f / C_, 0);
        updtr_k<<<dim3(32,32,B_), 256>>>(Mm, Sm, grad, lr, mom, fg, tM);

        // --- attention with persistent tokens (fused flash) ---
        ln_k<1><<<BC_, 256>>>(x, mc, g2, b2, h2, c0);
        hmma_k<10><<<dim3(24,16), 256, TM_SMEM>>>(h2, wqkv, (float*)attn, bqkv, nullptr,
            0, D_, D_, 0, 0, 0, 0, 1.f, 0);
        fattn_k<<<dim3(C_/128, BH_), 256, FA_SMEM>>>(attn, attn + KB_OFF, attn + VB_OFF, at);
        hmma_k<1><<<dim3(8,16), 256, TM_SMEM>>>(at, wo, ao, bo, nullptr,
            D_, D_, D_, 0, 0, 0, 0, 1.f, 0);
        hmma_k<2><<<dim3(8,16), 256, TM_SMEM>>>(mch, wg, gt, bg, nullptr,
            D_, D_, D_, 0, 0, 0, 0, 1.f, 0);
        cln_k<<<BC_, 256>>>(x, gt, ao, mc, o, h3, g3, b3, c0);

        // --- gated FFN (interleaved gate/up, fused silu) ---
        hmma_k<12><<<dim3(64,16), 256, TM_SMEM>>>(h3, wgui, (float*)fs, bgui, nullptr,
            FF_, D_, D_, 0, 0, 0, 0, 1.f, 0);
        hmma_k<5><<<dim3(8,16), 256, TM_SMEM>>>(fs, wdown, o, bdown, outp,
            D_, FF_, FF_, 0, 0, 0, 0, 1.f, c0);
    }
}